// round 7
// baseline (speedup 1.0000x reference)
#include <cuda_runtime.h>
#include <math.h>

#define B_   16
#define SQ_  128
#define SV_  128
#define DQ_  512
#define DV_  512
#define U_   256
#define QT   8                       // queries per attn CTA
#define CTX_ELEMS (B_*SQ_*DV_)       // context first, weights after

// Scratch (allocation-free rule: __device__ globals)
__device__ float g_s1[B_*SQ_*U_];   // [b][q][u]
__device__ float g_s2[B_*SV_*U_];   // [b][v][u]

__device__ __forceinline__ float tanh_fast(float x) {
    float y;
    asm("tanh.approx.f32 %0, %1;" : "=f"(y) : "f"(x));
    return y;
}

// -------------------------------------------------------------------------
// Fused dual scalar GEMM (R6, unchanged): z=0: g_s1 = query*W1+b1 ;
// z=1: g_s2 = values*W2+b2. 64x64x16 tile, 256 threads, 4x4 microtile,
// double-buffered smem. 256 CTAs.
// -------------------------------------------------------------------------
__global__ __launch_bounds__(256) void gemm_bias_kernel(
    const float* __restrict__ query, const float* __restrict__ values,
    const float* __restrict__ W1, const float* __restrict__ b1,
    const float* __restrict__ W2, const float* __restrict__ b2)
{
    __shared__ float As[2][16][68];   // k-major A tile (padded)
    __shared__ float Ws[2][16][64];

    const int which = blockIdx.z;
    const float* __restrict__ A    = which ? values : query;
    const float* __restrict__ W    = which ? W2 : W1;
    const float* __restrict__ bias = which ? b2 : b1;
    float* __restrict__ C          = which ? g_s2 : g_s1;

    const int tid  = threadIdx.x;
    const int bm   = blockIdx.y * 64;
    const int bn   = blockIdx.x * 64;
    const int tx   = tid & 15;          // n-dir
    const int ty   = tid >> 4;          // m-dir
    const int arow = tid >> 2;          // 0..63
    const int ak   = (tid & 3) << 2;    // 0,4,8,12
    const int wrow = tid >> 4;          // 0..15
    const int wn   = (tid & 15) << 2;   // 0..60

    const float* Ap = A + (size_t)(bm + arow) * DQ_ + ak;
    const float* Wp = W + (size_t)wrow * U_ + bn + wn;

    float4 ap = *(const float4*)Ap;
    float4 wp = *(const float4*)Wp;

    float c[4][4];
    #pragma unroll
    for (int i = 0; i < 4; i++)
        #pragma unroll
        for (int j = 0; j < 4; j++) c[i][j] = 0.f;

    // prologue: fill buffer 0
    As[0][ak+0][arow] = ap.x;
    As[0][ak+1][arow] = ap.y;
    As[0][ak+2][arow] = ap.z;
    As[0][ak+3][arow] = ap.w;
    *(float4*)&Ws[0][wrow][wn] = wp;
    __syncthreads();

    #pragma unroll 1
    for (int kt = 0; kt < DQ_/16; ++kt) {
        const int cur = kt & 1;
        const int nxt = cur ^ 1;
        if (kt + 1 < DQ_/16) {
            ap = *(const float4*)(Ap + (kt+1)*16);
            wp = *(const float4*)(Wp + (size_t)(kt+1)*16*U_);
        }
        #pragma unroll
        for (int k = 0; k < 16; k++) {
            float4 a4 = *(const float4*)&As[cur][k][ty << 2];
            float4 w4 = *(const float4*)&Ws[cur][k][tx << 2];
            float av[4] = {a4.x, a4.y, a4.z, a4.w};
            float wv[4] = {w4.x, w4.y, w4.z, w4.w};
            #pragma unroll
            for (int i = 0; i < 4; i++)
                #pragma unroll
                for (int j = 0; j < 4; j++)
                    c[i][j] += av[i] * wv[j];
        }
        if (kt + 1 < DQ_/16) {
            As[nxt][ak+0][arow] = ap.x;
            As[nxt][ak+1][arow] = ap.y;
            As[nxt][ak+2][arow] = ap.z;
            As[nxt][ak+3][arow] = ap.w;
            *(float4*)&Ws[nxt][wrow][wn] = wp;
            __syncthreads();
        }
    }

    float4 bv = *(const float4*)(bias + bn + (tx << 2));
    float bb[4] = {bv.x, bv.y, bv.z, bv.w};
    #pragma unroll
    for (int i = 0; i < 4; i++) {
        float4 o;
        o.x = c[i][0] + bb[0];
        o.y = c[i][1] + bb[1];
        o.z = c[i][2] + bb[2];
        o.w = c[i][3] + bb[3];
        *(float4*)&C[(size_t)(bm + (ty << 2) + i) * U_ + bn + (tx << 2)] = o;
    }
}

// -------------------------------------------------------------------------
// Fused attention v2: per CTA = (batch b, 8-query tile), 256 threads,
// grid 256 (all SMs). s2 is NOT staged — read via LDG (L2-resident) with
// register double-buffering. smem ~29.7KB static -> 2 CTAs/SM.
//   score (MUFU-bound) -> softmax (warp/q) -> weights out -> context GEMV.
// -------------------------------------------------------------------------
__global__ __launch_bounds__(256, 2) void attn_kernel(
    const float* __restrict__ values, const float* __restrict__ Vw,
    float* __restrict__ out)
{
    __shared__ float  s1s[QT * U_];     // 2048 floats
    __shared__ float  vws[U_];          // 256
    __shared__ float  sc[QT * SV_];     // 1024
    __shared__ float4 cbuf[QT * 128];   // 16KB (context reduce)

    const int tid = threadIdx.x;
    const int b   = blockIdx.x >> 4;
    const int q0  = (blockIdx.x & 15) << 3;

    // --- stage s1 tile + Vw ---
    const float4* s1g4 = (const float4*)(g_s1 + ((size_t)b * SQ_ + q0) * U_);
    for (int i = tid; i < QT * (U_/4); i += 256)
        ((float4*)s1s)[i] = s1g4[i];
    if (tid < U_/4)
        ((float4*)vws)[tid] = ((const float4*)Vw)[tid];
    __syncthreads();

    // --- scores: sc[q][v] = sum_u Vw[u]*tanh(s1[q][u] + s2[v][u]) ---
    {
        const int v  = tid & 127;
        const int qh = tid >> 7;            // 0/1 -> 4 q each
        const float4* s2g = (const float4*)(g_s2 + ((size_t)b * SV_ + v) * U_);
        const float*  s1q = s1s + (qh << 2) * U_;
        float acc[4] = {0.f, 0.f, 0.f, 0.f};

        float4 buf[2][4];                   // double-buffered 16-u blocks
        #pragma unroll
        for (int j = 0; j < 4; j++) buf[0][j] = s2g[j];

        #pragma unroll 1
        for (int blk = 0; blk < 16; blk++) {
            const int cur = blk & 1, nxt = cur ^ 1;
            if (blk < 15) {
                #pragma unroll
                for (int j = 0; j < 4; j++)
                    buf[nxt][j] = s2g[(blk + 1) * 4 + j];
            }
            #pragma unroll
            for (int j = 0; j < 4; j++) {
                const int u = (blk << 4) + (j << 2);
                float4 f2 = buf[cur][j];
                float4 wv = *(const float4*)(vws + u);
                #pragma unroll
                for (int qi = 0; qi < 4; qi++) {
                    float4 s1v = *(const float4*)(s1q + qi * U_ + u);
                    acc[qi] += wv.x * tanh_fast(s1v.x + f2.x)
                             + wv.y * tanh_fast(s1v.y + f2.y)
                             + wv.z * tanh_fast(s1v.z + f2.z)
                             + wv.w * tanh_fast(s1v.w + f2.w);
                }
            }
        }
        #pragma unroll
        for (int qi = 0; qi < 4; qi++)
            sc[((qh << 2) + qi) * SV_ + v] = acc[qi];
    }
    __syncthreads();

    // --- softmax over v; one warp per q row (8 warps) ---
    {
        const int q = tid >> 5, lane = tid & 31;
        float x0 = sc[q*SV_ +      lane];
        float x1 = sc[q*SV_ + 32 + lane];
        float x2 = sc[q*SV_ + 64 + lane];
        float x3 = sc[q*SV_ + 96 + lane];
        float m = fmaxf(fmaxf(x0, x1), fmaxf(x2, x3));
        #pragma unroll
        for (int off = 16; off; off >>= 1)
            m = fmaxf(m, __shfl_xor_sync(0xffffffffu, m, off));
        float e0 = __expf(x0 - m), e1 = __expf(x1 - m);
        float e2 = __expf(x2 - m), e3 = __expf(x3 - m);
        float s = (e0 + e1) + (e2 + e3);
        #pragma unroll
        for (int off = 16; off; off >>= 1)
            s += __shfl_xor_sync(0xffffffffu, s, off);
        float inv = 1.0f / s;
        e0 *= inv; e1 *= inv; e2 *= inv; e3 *= inv;
        sc[q*SV_ +      lane] = e0;
        sc[q*SV_ + 32 + lane] = e1;
        sc[q*SV_ + 64 + lane] = e2;
        sc[q*SV_ + 96 + lane] = e3;
        float* wout = out + CTX_ELEMS + (size_t)(b * SQ_ + q0 + q) * SV_;
        wout[lane]      = e0;
        wout[32 + lane] = e1;
        wout[64 + lane] = e2;
        wout[96 + lane] = e3;
    }
    __syncthreads();

    // --- context[q][d] = sum_v w[q][v] * values[b][v][d]; v-halves ---
    {
        const int half = tid >> 7;          // v-range half (64 v each)
        const int dg   = tid & 127;         // float4 group over DV
        float4 acc[QT];
        #pragma unroll
        for (int q = 0; q < QT; q++) acc[q] = make_float4(0.f, 0.f, 0.f, 0.f);

        const float* vb  = values + ((size_t)(b * SV_) + (half << 6)) * DV_ + (dg << 2);
        const float* scv = sc + (half << 6);
        #pragma unroll 4
        for (int vv = 0; vv < 64; vv++) {
            float4 val = *(const float4*)(vb + (size_t)vv * DV_);
            #pragma unroll
            for (int q = 0; q < QT; q++) {
                float wq = scv[q * SV_ + vv];
                acc[q].x += wq * val.x;
                acc[q].y += wq * val.y;
                acc[q].z += wq * val.z;
                acc[q].w += wq * val.w;
            }
        }
        if (half) {
            #pragma unroll
            for (int q = 0; q < QT; q++) cbuf[q * 128 + dg] = acc[q];
        }
        __syncthreads();
        if (!half) {
            #pragma unroll
            for (int q = 0; q < QT; q++) {
                float4 o = cbuf[q * 128 + dg];
                o.x += acc[q].x; o.y += acc[q].y;
                o.z += acc[q].z; o.w += acc[q].w;
                *(float4*)&out[(size_t)(b * SQ_ + q0 + q) * DV_ + (dg << 2)] = o;
            }
        }
    }
}

// -------------------------------------------------------------------------
extern "C" void kernel_launch(void* const* d_in, const int* in_sizes, int n_in,
                              void* d_out, int out_size)
{
    const float* query  = (const float*)d_in[0];
    const float* values = (const float*)d_in[1];
    const float* W1     = (const float*)d_in[2];
    const float* b1     = (const float*)d_in[3];
    const float* W2     = (const float*)d_in[4];
    const float* b2     = (const float*)d_in[5];
    const float* Vw     = (const float*)d_in[6];
    // d_in[7] = Vb: softmax is shift-invariant; score itself is not an
    // output, so Vb provably cancels. Unused.
    float* out = (float*)d_out;

    dim3 gemm_grid(U_/64, (B_*SQ_)/64, 2);          // 4 x 32 x 2 = 256 CTAs
    gemm_bias_kernel<<<gemm_grid, 256>>>(query, values, W1, b1, W2, b2);

    attn_kernel<<<B_ * (SQ_/QT), 256>>>(values, Vw, out);   // 256 CTAs
}

// round 8
// speedup vs baseline: 1.0506x; 1.0506x over previous
#include <cuda_runtime.h>
#include <math.h>

#define B_   16
#define SQ_  128
#define SV_  128
#define DQ_  512
#define DV_  512
#define U_   256
#define QT   8                       // queries per softctx CTA
#define CTX_ELEMS (B_*SQ_*DV_)       // context first, weights after

// Scratch (allocation-free rule: __device__ globals)
__device__ float g_s1[B_*SQ_*U_];    // [b][q][u]
__device__ float g_s2[B_*SV_*U_];    // [b][v][u]
__device__ float g_sc[B_*SQ_*SV_];   // raw scores [b][q][v]

__device__ __forceinline__ float tanh_fast(float x) {
    float y;
    asm("tanh.approx.f32 %0, %1;" : "=f"(y) : "f"(x));
    return y;
}

// -------------------------------------------------------------------------
// Fused dual scalar GEMM: z=0: g_s1 = query*W1+b1 ; z=1: g_s2 = values*W2+b2
// 32x64x16 tile, 128 threads, 4x4 scalar microtile, double-buffered smem.
// 512 CTAs -> ~3.5 CTAs/SM (~14 warps/SM) for issue saturation.
// -------------------------------------------------------------------------
__global__ __launch_bounds__(128) void gemm_bias_kernel(
    const float* __restrict__ query, const float* __restrict__ values,
    const float* __restrict__ W1, const float* __restrict__ b1,
    const float* __restrict__ W2, const float* __restrict__ b2)
{
    __shared__ float As[2][16][36];   // k-major A tile (stride 144B, 16B-aligned)
    __shared__ float Ws[2][16][64];

    const int which = blockIdx.z;
    const float* __restrict__ A    = which ? values : query;
    const float* __restrict__ W    = which ? W2 : W1;
    const float* __restrict__ bias = which ? b2 : b1;
    float* __restrict__ C          = which ? g_s2 : g_s1;

    const int tid  = threadIdx.x;
    const int bm   = blockIdx.y * 32;
    const int bn   = blockIdx.x * 64;
    const int tx   = tid & 15;          // n-dir: 4 cols
    const int ty   = tid >> 4;          // m-dir: 0..7 -> 4 rows
    const int arow = tid >> 2;          // 0..31
    const int ak   = (tid & 3) << 2;    // 0,4,8,12
    const int wrow = tid >> 4;          // 0..7 (and +8)
    const int wn   = (tid & 15) << 2;   // 0..60

    const float* Ap = A + (size_t)(bm + arow) * DQ_ + ak;
    const float* Wp = W + (size_t)wrow * U_ + bn + wn;

    float4 ap  = *(const float4*)Ap;
    float4 wp0 = *(const float4*)Wp;
    float4 wp1 = *(const float4*)(Wp + 8 * U_);

    float c[4][4];
    #pragma unroll
    for (int i = 0; i < 4; i++)
        #pragma unroll
        for (int j = 0; j < 4; j++) c[i][j] = 0.f;

    // prologue: fill buffer 0
    As[0][ak+0][arow] = ap.x;
    As[0][ak+1][arow] = ap.y;
    As[0][ak+2][arow] = ap.z;
    As[0][ak+3][arow] = ap.w;
    *(float4*)&Ws[0][wrow][wn]     = wp0;
    *(float4*)&Ws[0][wrow + 8][wn] = wp1;
    __syncthreads();

    #pragma unroll 1
    for (int kt = 0; kt < DQ_/16; ++kt) {
        const int cur = kt & 1;
        const int nxt = cur ^ 1;
        if (kt + 1 < DQ_/16) {
            ap  = *(const float4*)(Ap + (kt+1)*16);
            wp0 = *(const float4*)(Wp + (size_t)(kt+1)*16*U_);
            wp1 = *(const float4*)(Wp + (size_t)((kt+1)*16 + 8)*U_);
        }
        #pragma unroll
        for (int k = 0; k < 16; k++) {
            float4 a4 = *(const float4*)&As[cur][k][ty << 2];
            float4 w4 = *(const float4*)&Ws[cur][k][tx << 2];
            float av[4] = {a4.x, a4.y, a4.z, a4.w};
            float wv[4] = {w4.x, w4.y, w4.z, w4.w};
            #pragma unroll
            for (int i = 0; i < 4; i++)
                #pragma unroll
                for (int j = 0; j < 4; j++)
                    c[i][j] += av[i] * wv[j];
        }
        if (kt + 1 < DQ_/16) {
            As[nxt][ak+0][arow] = ap.x;
            As[nxt][ak+1][arow] = ap.y;
            As[nxt][ak+2][arow] = ap.z;
            As[nxt][ak+3][arow] = ap.w;
            *(float4*)&Ws[nxt][wrow][wn]     = wp0;
            *(float4*)&Ws[nxt][wrow + 8][wn] = wp1;
            __syncthreads();
        }
    }

    float4 bv = *(const float4*)(bias + bn + (tx << 2));
    float bb[4] = {bv.x, bv.y, bv.z, bv.w};
    #pragma unroll
    for (int i = 0; i < 4; i++) {
        float4 o;
        o.x = c[i][0] + bb[0];
        o.y = c[i][1] + bb[1];
        o.z = c[i][2] + bb[2];
        o.w = c[i][3] + bb[3];
        *(float4*)&C[(size_t)(bm + (ty << 2) + i) * U_ + bn + (tx << 2)] = o;
    }
}

// -------------------------------------------------------------------------
// Score kernel: CTA = (batch b, 16-q tile, v-half). Stages a 64-v half of
// s2 (~66KB) + s1 tile -> ~84KB smem -> 2 CTAs/SM, grid 256 (all SMs).
// sc[q][v] = sum_u Vw[u]*tanh(s1[q][u]+s2[v][u])  -> g_sc (raw scores).
// -------------------------------------------------------------------------
#define S2HSTRIDE 260

__global__ __launch_bounds__(256, 2) void score_kernel(
    const float* __restrict__ Vw)
{
    extern __shared__ float sm[];
    float* s2h = sm;                         // 64*260  = 16640 floats
    float* s1s = sm + 64 * S2HSTRIDE;        // 16*256  = 4096
    float* vws = s1s + 16 * U_;              // 256

    const int bx  = blockIdx.x;
    const int b   = bx >> 4;
    const int qt  = (bx >> 1) & 7;
    const int vh  = bx & 1;
    const int q0  = qt << 4;
    const int tid = threadIdx.x;

    // stage s2 half (rows vh*64 .. vh*64+63), s1 tile, Vw
    const float4* s2g4 = (const float4*)(g_s2 + ((size_t)b * SV_ + (vh << 6)) * U_);
    for (int i = tid; i < 64 * (U_/4); i += 256) {
        int v = i >> 6, u4 = i & 63;
        *(float4*)&s2h[v * S2HSTRIDE + (u4 << 2)] = s2g4[i];
    }
    const float4* s1g4 = (const float4*)(g_s1 + ((size_t)b * SQ_ + q0) * U_);
    for (int i = tid; i < 16 * (U_/4); i += 256)
        ((float4*)s1s)[i] = s1g4[i];
    if (tid < U_/4)
        ((float4*)vws)[tid] = ((const float4*)Vw)[tid];
    __syncthreads();

    const int v  = tid & 63;
    const int qg = tid >> 6;                 // 0..3 -> 4 q each
    const float* s1q = s1s + (qg << 2) * U_;
    const float* s2r = s2h + v * S2HSTRIDE;
    float acc[4] = {0.f, 0.f, 0.f, 0.f};

    #pragma unroll 2
    for (int u = 0; u < U_; u += 4) {
        float4 f2 = *(const float4*)(s2r + u);
        float4 wv = *(const float4*)(vws + u);
        #pragma unroll
        for (int qi = 0; qi < 4; qi++) {
            float4 s1v = *(const float4*)(s1q + qi * U_ + u);
            acc[qi] += wv.x * tanh_fast(s1v.x + f2.x)
                     + wv.y * tanh_fast(s1v.y + f2.y)
                     + wv.z * tanh_fast(s1v.z + f2.z)
                     + wv.w * tanh_fast(s1v.w + f2.w);
        }
    }
    float* scp = g_sc + ((size_t)(b * SQ_ + q0 + (qg << 2)) * SV_) + (vh << 6) + v;
    #pragma unroll
    for (int qi = 0; qi < 4; qi++)
        scp[(size_t)qi * SV_] = acc[qi];
}

// -------------------------------------------------------------------------
// Softmax + context kernel: CTA = (batch b, 8-q tile), grid 256.
// Reads raw scores from g_sc (L2), softmax per warp, writes weights,
// context GEMV with v-half split + smem reduce.
// -------------------------------------------------------------------------
__global__ __launch_bounds__(256, 2) void softctx_kernel(
    const float* __restrict__ values, float* __restrict__ out)
{
    __shared__ float  sc[QT * SV_];     // 1024 floats
    __shared__ float4 cbuf[QT * 128];   // 16KB

    const int tid = threadIdx.x;
    const int b   = blockIdx.x >> 4;
    const int q0  = (blockIdx.x & 15) << 3;

    // load raw scores (8 rows x 128) from g_sc
    const float4* scg = (const float4*)(g_sc + (size_t)(b * SQ_ + q0) * SV_);
    ((float4*)sc)[tid] = scg[tid];      // 256 float4 = 8*128 floats
    __syncthreads();

    // --- softmax over v; one warp per q row (8 warps) ---
    {
        const int q = tid >> 5, lane = tid & 31;
        float x0 = sc[q*SV_ +      lane];
        float x1 = sc[q*SV_ + 32 + lane];
        float x2 = sc[q*SV_ + 64 + lane];
        float x3 = sc[q*SV_ + 96 + lane];
        float m = fmaxf(fmaxf(x0, x1), fmaxf(x2, x3));
        #pragma unroll
        for (int off = 16; off; off >>= 1)
            m = fmaxf(m, __shfl_xor_sync(0xffffffffu, m, off));
        float e0 = __expf(x0 - m), e1 = __expf(x1 - m);
        float e2 = __expf(x2 - m), e3 = __expf(x3 - m);
        float s = (e0 + e1) + (e2 + e3);
        #pragma unroll
        for (int off = 16; off; off >>= 1)
            s += __shfl_xor_sync(0xffffffffu, s, off);
        float inv = 1.0f / s;
        e0 *= inv; e1 *= inv; e2 *= inv; e3 *= inv;
        sc[q*SV_ +      lane] = e0;
        sc[q*SV_ + 32 + lane] = e1;
        sc[q*SV_ + 64 + lane] = e2;
        sc[q*SV_ + 96 + lane] = e3;
        float* wout = out + CTX_ELEMS + (size_t)(b * SQ_ + q0 + q) * SV_;
        wout[lane]      = e0;
        wout[32 + lane] = e1;
        wout[64 + lane] = e2;
        wout[96 + lane] = e3;
    }
    __syncthreads();

    // --- context[q][d] = sum_v w[q][v] * values[b][v][d]; v-halves ---
    {
        const int half = tid >> 7;          // v-range half (64 v each)
        const int dg   = tid & 127;         // float4 group over DV
        float4 acc[QT];
        #pragma unroll
        for (int q = 0; q < QT; q++) acc[q] = make_float4(0.f, 0.f, 0.f, 0.f);

        const float* vb  = values + ((size_t)(b * SV_) + (half << 6)) * DV_ + (dg << 2);
        const float* scv = sc + (half << 6);
        #pragma unroll 4
        for (int vv = 0; vv < 64; vv++) {
            float4 val = *(const float4*)(vb + (size_t)vv * DV_);
            #pragma unroll
            for (int q = 0; q < QT; q++) {
                float wq = scv[q * SV_ + vv];
                acc[q].x += wq * val.x;
                acc[q].y += wq * val.y;
                acc[q].z += wq * val.z;
                acc[q].w += wq * val.w;
            }
        }
        if (half) {
            #pragma unroll
            for (int q = 0; q < QT; q++) cbuf[q * 128 + dg] = acc[q];
        }
        __syncthreads();
        if (!half) {
            #pragma unroll
            for (int q = 0; q < QT; q++) {
                float4 o = cbuf[q * 128 + dg];
                o.x += acc[q].x; o.y += acc[q].y;
                o.z += acc[q].z; o.w += acc[q].w;
                *(float4*)&out[(size_t)(b * SQ_ + q0 + q) * DV_ + (dg << 2)] = o;
            }
        }
    }
}

// -------------------------------------------------------------------------
extern "C" void kernel_launch(void* const* d_in, const int* in_sizes, int n_in,
                              void* d_out, int out_size)
{
    const float* query  = (const float*)d_in[0];
    const float* values = (const float*)d_in[1];
    const float* W1     = (const float*)d_in[2];
    const float* b1     = (const float*)d_in[3];
    const float* W2     = (const float*)d_in[4];
    const float* b2     = (const float*)d_in[5];
    const float* W2b    = (const float*)d_in[5];
    const float* Vw     = (const float*)d_in[6];
    // d_in[7] = Vb: softmax is shift-invariant; score itself is not an
    // output, so Vb provably cancels. Unused.
    float* out = (float*)d_out;
    (void)W2b;

    dim3 gemm_grid(U_/64, (B_*SQ_)/32, 2);          // 4 x 64 x 2 = 512 CTAs
    gemm_bias_kernel<<<gemm_grid, 128>>>(query, values, W1, b1, W2, b2);

    const size_t score_smem =
        (size_t)(64 * S2HSTRIDE + 16 * U_ + U_) * sizeof(float);  // ~84KB
    cudaFuncSetAttribute(score_kernel,
                         cudaFuncAttributeMaxDynamicSharedMemorySize,
                         (int)score_smem);
    score_kernel<<<B_ * 8 * 2, 256, score_smem>>>(Vw);      // 256 CTAs

    softctx_kernel<<<B_ * (SQ_/QT), 256>>>(values, out);    // 256 CTAs
}

// round 9
// speedup vs baseline: 1.1539x; 1.0983x over previous
#include <cuda_runtime.h>
#include <math.h>

#define B_   16
#define SQ_  128
#define SV_  128
#define DQ_  512
#define DV_  512
#define U_   256
#define QT   8                       // queries per attn CTA
#define CTX_ELEMS (B_*SQ_*DV_)       // context first, weights after

// Scratch (allocation-free rule: __device__ globals)
__device__ float g_s1[B_*SQ_*U_];    // [b][q][u]
__device__ float g_s2[B_*SV_*U_];    // [b][v][u]

__device__ __forceinline__ float tanh_fast(float x) {
    float y;
    asm("tanh.approx.f32 %0, %1;" : "=f"(y) : "f"(x));
    return y;
}

// -------------------------------------------------------------------------
// Fused dual scalar GEMM (R8, unchanged — measured best):
// z=0: g_s1 = query*W1+b1 ; z=1: g_s2 = values*W2+b2
// 32x64x16 tile, 128 threads, 4x4 scalar microtile, double-buffered smem.
// 512 CTAs -> ~3.5 CTAs/SM.
// -------------------------------------------------------------------------
__global__ __launch_bounds__(128) void gemm_bias_kernel(
    const float* __restrict__ query, const float* __restrict__ values,
    const float* __restrict__ W1, const float* __restrict__ b1,
    const float* __restrict__ W2, const float* __restrict__ b2)
{
    __shared__ float As[2][16][36];   // k-major A tile (stride 144B, 16B-aligned)
    __shared__ float Ws[2][16][64];

    const int which = blockIdx.z;
    const float* __restrict__ A    = which ? values : query;
    const float* __restrict__ W    = which ? W2 : W1;
    const float* __restrict__ bias = which ? b2 : b1;
    float* __restrict__ C          = which ? g_s2 : g_s1;

    const int tid  = threadIdx.x;
    const int bm   = blockIdx.y * 32;
    const int bn   = blockIdx.x * 64;
    const int tx   = tid & 15;          // n-dir: 4 cols
    const int ty   = tid >> 4;          // m-dir: 0..7 -> 4 rows
    const int arow = tid >> 2;          // 0..31
    const int ak   = (tid & 3) << 2;    // 0,4,8,12
    const int wrow = tid >> 4;          // 0..7 (and +8)
    const int wn   = (tid & 15) << 2;   // 0..60

    const float* Ap = A + (size_t)(bm + arow) * DQ_ + ak;
    const float* Wp = W + (size_t)wrow * U_ + bn + wn;

    float4 ap  = *(const float4*)Ap;
    float4 wp0 = *(const float4*)Wp;
    float4 wp1 = *(const float4*)(Wp + 8 * U_);

    float c[4][4];
    #pragma unroll
    for (int i = 0; i < 4; i++)
        #pragma unroll
        for (int j = 0; j < 4; j++) c[i][j] = 0.f;

    As[0][ak+0][arow] = ap.x;
    As[0][ak+1][arow] = ap.y;
    As[0][ak+2][arow] = ap.z;
    As[0][ak+3][arow] = ap.w;
    *(float4*)&Ws[0][wrow][wn]     = wp0;
    *(float4*)&Ws[0][wrow + 8][wn] = wp1;
    __syncthreads();

    #pragma unroll 1
    for (int kt = 0; kt < DQ_/16; ++kt) {
        const int cur = kt & 1;
        const int nxt = cur ^ 1;
        if (kt + 1 < DQ_/16) {
            ap  = *(const float4*)(Ap + (kt+1)*16);
            wp0 = *(const float4*)(Wp + (size_t)(kt+1)*16*U_);
            wp1 = *(const float4*)(Wp + (size_t)((kt+1)*16 + 8)*U_);
        }
        #pragma unroll
        for (int k = 0; k < 16; k++) {
            float4 a4 = *(const float4*)&As[cur][k][ty << 2];
            float4 w4 = *(const float4*)&Ws[cur][k][tx << 2];
            float av[4] = {a4.x, a4.y, a4.z, a4.w};
            float wv[4] = {w4.x, w4.y, w4.z, w4.w};
            #pragma unroll
            for (int i = 0; i < 4; i++)
                #pragma unroll
                for (int j = 0; j < 4; j++)
                    c[i][j] += av[i] * wv[j];
        }
        if (kt + 1 < DQ_/16) {
            As[nxt][ak+0][arow] = ap.x;
            As[nxt][ak+1][arow] = ap.y;
            As[nxt][ak+2][arow] = ap.z;
            As[nxt][ak+3][arow] = ap.w;
            *(float4*)&Ws[nxt][wrow][wn]     = wp0;
            *(float4*)&Ws[nxt][wrow + 8][wn] = wp1;
            __syncthreads();
        }
    }

    float4 bv = *(const float4*)(bias + bn + (tx << 2));
    float bb[4] = {bv.x, bv.y, bv.z, bv.w};
    #pragma unroll
    for (int i = 0; i < 4; i++) {
        float4 o;
        o.x = c[i][0] + bb[0];
        o.y = c[i][1] + bb[1];
        o.z = c[i][2] + bb[2];
        o.w = c[i][3] + bb[3];
        *(float4*)&C[(size_t)(bm + (ty << 2) + i) * U_ + bn + (tx << 2)] = o;
    }
}

// -------------------------------------------------------------------------
// Fused attention v3: CTA = (batch b, 8-q tile), grid 256, 256 threads.
// s2 staged in TWO 64-v chunks through one smem buffer -> ~94KB smem ->
// 2 CTAs/SM co-resident (cross-CTA pipe overlap), all 148 SMs covered.
//   score (MUFU-bound) -> softmax (warp/q) -> weights out -> context GEMV.
// -------------------------------------------------------------------------
#define S2HSTRIDE 260
#define SM_S1   (64 * S2HSTRIDE)          // 16640
#define SM_VW   (SM_S1 + QT * U_)         // 18688
#define SM_SC   (SM_VW + U_)              // 18944
#define SM_CBUF (SM_SC + QT * SV_)        // 19968 (16B aligned: 19968*4)
#define SM_TOTAL_F (SM_CBUF + QT * 128 * 4)  // 24064 floats = 96256 B

__global__ __launch_bounds__(256, 2) void attn_kernel(
    const float* __restrict__ values, const float* __restrict__ Vw,
    float* __restrict__ out)
{
    extern __shared__ float sm[];
    float*  s2h  = sm;                    // 64*260 floats
    float*  s1s  = sm + SM_S1;            // 8*256
    float*  vws  = sm + SM_VW;            // 256
    float*  sc   = sm + SM_SC;            // 8*128
    float4* cbuf = (float4*)(sm + SM_CBUF); // 8*128 float4

    const int tid = threadIdx.x;
    const int b   = blockIdx.x >> 4;
    const int q0  = (blockIdx.x & 15) << 3;

    // --- stage s1 tile + Vw ---
    const float4* s1g4 = (const float4*)(g_s1 + ((size_t)b * SQ_ + q0) * U_);
    for (int i = tid; i < QT * (U_/4); i += 256)
        ((float4*)s1s)[i] = s1g4[i];
    if (tid < U_/4)
        ((float4*)vws)[tid] = ((const float4*)Vw)[tid];

    // --- scores in two v-chunks through one s2 buffer ---
    #pragma unroll 1
    for (int vh = 0; vh < 2; vh++) {
        const float4* s2g4 =
            (const float4*)(g_s2 + ((size_t)b * SV_ + (vh << 6)) * U_);
        for (int i = tid; i < 64 * (U_/4); i += 256) {
            int v = i >> 6, u4 = i & 63;
            *(float4*)&s2h[v * S2HSTRIDE + (u4 << 2)] = s2g4[i];
        }
        __syncthreads();

        const int v  = tid & 63;
        const int qg = tid >> 6;            // 0..3 -> 2 q each
        const float* s1q = s1s + (qg << 1) * U_;
        const float* s2r = s2h + v * S2HSTRIDE;
        float acc[2] = {0.f, 0.f};
        #pragma unroll 4
        for (int u = 0; u < U_; u += 4) {
            float4 f2 = *(const float4*)(s2r + u);
            float4 wv = *(const float4*)(vws + u);
            #pragma unroll
            for (int qi = 0; qi < 2; qi++) {
                float4 s1v = *(const float4*)(s1q + qi * U_ + u);
                acc[qi] += wv.x * tanh_fast(s1v.x + f2.x)
                         + wv.y * tanh_fast(s1v.y + f2.y)
                         + wv.z * tanh_fast(s1v.z + f2.z)
                         + wv.w * tanh_fast(s1v.w + f2.w);
            }
        }
        #pragma unroll
        for (int qi = 0; qi < 2; qi++)
            sc[((qg << 1) + qi) * SV_ + (vh << 6) + v] = acc[qi];
        __syncthreads();                    // buffer reuse / sc complete
    }

    // --- softmax over v; one warp per q row (8 warps) ---
    {
        const int q = tid >> 5, lane = tid & 31;
        float x0 = sc[q*SV_ +      lane];
        float x1 = sc[q*SV_ + 32 + lane];
        float x2 = sc[q*SV_ + 64 + lane];
        float x3 = sc[q*SV_ + 96 + lane];
        float m = fmaxf(fmaxf(x0, x1), fmaxf(x2, x3));
        #pragma unroll
        for (int off = 16; off; off >>= 1)
            m = fmaxf(m, __shfl_xor_sync(0xffffffffu, m, off));
        float e0 = __expf(x0 - m), e1 = __expf(x1 - m);
        float e2 = __expf(x2 - m), e3 = __expf(x3 - m);
        float s = (e0 + e1) + (e2 + e3);
        #pragma unroll
        for (int off = 16; off; off >>= 1)
            s += __shfl_xor_sync(0xffffffffu, s, off);
        float inv = 1.0f / s;
        e0 *= inv; e1 *= inv; e2 *= inv; e3 *= inv;
        sc[q*SV_ +      lane] = e0;
        sc[q*SV_ + 32 + lane] = e1;
        sc[q*SV_ + 64 + lane] = e2;
        sc[q*SV_ + 96 + lane] = e3;
        float* wout = out + CTX_ELEMS + (size_t)(b * SQ_ + q0 + q) * SV_;
        wout[lane]      = e0;
        wout[32 + lane] = e1;
        wout[64 + lane] = e2;
        wout[96 + lane] = e3;
    }
    __syncthreads();

    // --- context[q][d] = sum_v w[q][v] * values[b][v][d]; v-halves ---
    {
        const int half = tid >> 7;          // v-range half (64 v each)
        const int dg   = tid & 127;         // float4 group over DV
        float4 acc[QT];
        #pragma unroll
        for (int q = 0; q < QT; q++) acc[q] = make_float4(0.f, 0.f, 0.f, 0.f);

        const float* vb  = values + ((size_t)(b * SV_) + (half << 6)) * DV_ + (dg << 2);
        const float* scv = sc + (half << 6);
        #pragma unroll 4
        for (int vv = 0; vv < 64; vv++) {
            float4 val = *(const float4*)(vb + (size_t)vv * DV_);
            #pragma unroll
            for (int q = 0; q < QT; q++) {
                float wq = scv[q * SV_ + vv];
                acc[q].x += wq * val.x;
                acc[q].y += wq * val.y;
                acc[q].z += wq * val.z;
                acc[q].w += wq * val.w;
            }
        }
        if (half) {
            #pragma unroll
            for (int q = 0; q < QT; q++) cbuf[q * 128 + dg] = acc[q];
        }
        __syncthreads();
        if (!half) {
            #pragma unroll
            for (int q = 0; q < QT; q++) {
                float4 o = cbuf[q * 128 + dg];
                o.x += acc[q].x; o.y += acc[q].y;
                o.z += acc[q].z; o.w += acc[q].w;
                *(float4*)&out[(size_t)(b * SQ_ + q0 + q) * DV_ + (dg << 2)] = o;
            }
        }
    }
}

// -------------------------------------------------------------------------
extern "C" void kernel_launch(void* const* d_in, const int* in_sizes, int n_in,
                              void* d_out, int out_size)
{
    const float* query  = (const float*)d_in[0];
    const float* values = (const float*)d_in[1];
    const float* W1     = (const float*)d_in[2];
    const float* b1     = (const float*)d_in[3];
    const float* W2     = (const float*)d_in[4];
    const float* b2     = (const float*)d_in[5];
    const float* Vw     = (const float*)d_in[6];
    // d_in[7] = Vb: softmax is shift-invariant; score itself is not an
    // output, so Vb provably cancels. Unused.
    float* out = (float*)d_out;

    dim3 gemm_grid(U_/64, (B_*SQ_)/32, 2);          // 4 x 64 x 2 = 512 CTAs
    gemm_bias_kernel<<<gemm_grid, 128>>>(query, values, W1, b1, W2, b2);

    const size_t attn_smem = (size_t)SM_TOTAL_F * sizeof(float);  // 96256 B
    cudaFuncSetAttribute(attn_kernel,
                         cudaFuncAttributeMaxDynamicSharedMemorySize,
                         (int)attn_smem);
    attn_kernel<<<B_ * (SQ_/QT), 256, attn_smem>>>(values, Vw, out);  // 256 CTAs
}

// round 12
// speedup vs baseline: 1.3637x; 1.1819x over previous
#include <cuda_runtime.h>
#include <cuda_bf16.h>
#include <math.h>
#include <cstdint>

#define B_   16
#define SQ_  128
#define SV_  128
#define DQ_  512
#define DV_  512
#define U_   256
#define QT   8
#define CTX_ELEMS (B_*SQ_*DV_)

typedef unsigned long long ull;

// Scratch (allocation-free rule: __device__ globals)
__device__ float g_s1[B_*SQ_*U_];    // [b][q][u]
__device__ float g_s2[B_*SV_*U_];    // [b][v][u]

__device__ __forceinline__ float tanh_fast(float x) {
    float y;
    asm("tanh.approx.f32 %0, %1;" : "=f"(y) : "f"(x));
    return y;
}
__device__ __forceinline__ uint32_t smem_u32(const void* p) {
    uint32_t a;
    asm("{ .reg .u64 t; cvta.to.shared.u64 t, %1; cvt.u32.u64 %0, t; }"
        : "=r"(a) : "l"(p));
    return a;
}
__device__ __forceinline__ void ldsm_x4(uint32_t* r, uint32_t addr) {
    asm volatile("ldmatrix.sync.aligned.m8n8.x4.shared.b16 {%0,%1,%2,%3}, [%4];"
        : "=r"(r[0]), "=r"(r[1]), "=r"(r[2]), "=r"(r[3]) : "r"(addr));
}
__device__ __forceinline__ void ldsm_x4t(uint32_t* r, uint32_t addr) {
    asm volatile("ldmatrix.sync.aligned.m8n8.x4.trans.shared.b16 {%0,%1,%2,%3}, [%4];"
        : "=r"(r[0]), "=r"(r[1]), "=r"(r[2]), "=r"(r[3]) : "r"(addr));
}
__device__ __forceinline__ void mma16816(float* c, const uint32_t* a,
                                         const uint32_t* b) {
    asm volatile(
        "mma.sync.aligned.m16n8k16.row.col.f32.bf16.bf16.f32 "
        "{%0,%1,%2,%3}, {%4,%5,%6,%7}, {%8,%9}, {%0,%1,%2,%3};"
        : "+f"(c[0]), "+f"(c[1]), "+f"(c[2]), "+f"(c[3])
        : "r"(a[0]), "r"(a[1]), "r"(a[2]), "r"(a[3]), "r"(b[0]), "r"(b[1]));
}
__device__ __forceinline__ uint32_t pack_bf16hi(float x, float y) {
    return (uint32_t)__bfloat16_as_ushort(__float2bfloat16(x))
         | ((uint32_t)__bfloat16_as_ushort(__float2bfloat16(y)) << 16);
}

// ========================================================================
// Tensor-core dual GEMM via baseline mma.sync (split bf16):
//   z=0: g_s1 = query*W1+b1 ; z=1: g_s2 = values*W2+b2
// CTA tile 64x64, 128 threads (4 warps, 32x32 warp tiles), K chunks of 128.
// A smem [64m][128k] bf16 hi/lo (stride 272B); B smem [128k][64n] bf16
// hi/lo (stride 144B, ldmatrix.trans). D = Ah*Bh + Ah*Bl + Al*Bh (fp32).
// ========================================================================
#define KC    128
#define ASTR  272
#define BSTR  144
#define A_HI  0
#define A_LO  (64 * ASTR)                 // 17408
#define BSM_HI (2 * 64 * ASTR)            // 34816
#define BSM_LO (BSM_HI + KC * BSTR)       // 53248
#define SM_GEMM_TOTAL (BSM_LO + KC * BSTR) // 71680 B

__global__ __launch_bounds__(128) void gemm_tc_kernel(
    const float* __restrict__ query, const float* __restrict__ values,
    const float* __restrict__ W1, const float* __restrict__ b1,
    const float* __restrict__ W2, const float* __restrict__ b2)
{
    extern __shared__ char smem[];
    const uint32_t smb = smem_u32(smem);
    const int tid = threadIdx.x;
    const int l   = tid & 31;
    const int w   = tid >> 5;
    const int mw  = w >> 1;            // 0/1 -> warp rows mw*32
    const int nw  = w & 1;             // 0/1 -> warp cols nw*32

    const int which = blockIdx.z;
    const float* __restrict__ A    = which ? values : query;
    const float* __restrict__ W    = which ? W2 : W1;
    const float* __restrict__ bias = which ? b2 : b1;
    float* __restrict__ C          = which ? g_s2 : g_s1;

    const int bm = blockIdx.y * 64;
    const int bn = blockIdx.x * 64;

    float acc[2][4][4];
    #pragma unroll
    for (int mi = 0; mi < 2; mi++)
        #pragma unroll
        for (int ni = 0; ni < 4; ni++)
            #pragma unroll
            for (int j = 0; j < 4; j++) acc[mi][ni][j] = 0.f;

    // ldmatrix per-lane base addresses
    const int arow = mw*32 + (l & 7) + 8*((l >> 3) & 1);
    const uint32_t aoff = (uint32_t)(arow * ASTR + ((l >> 4) << 4));
    const int brow = (l & 7) + 8*((l >> 3) & 1);
    const uint32_t boff = (uint32_t)(brow * BSTR + nw*64 + ((l >> 4) << 4));

    #pragma unroll 1
    for (int ch = 0; ch < 4; ch++) {
        const int k0 = ch * KC;
        __syncthreads();   // smem reuse barrier

        // --- stage A chunk [64m x 128k] hi/lo ---
        #pragma unroll 4
        for (int i = tid; i < 64*32; i += 128) {
            const int row = i >> 5;
            const int k4  = (i & 31) << 2;
            float4 a = *(const float4*)(A + (size_t)(bm + row) * DQ_ + k0 + k4);
            uint32_t h01 = pack_bf16hi(a.x, a.y);
            uint32_t h23 = pack_bf16hi(a.z, a.w);
            float rx = a.x - __bfloat162float(__float2bfloat16(a.x));
            float ry = a.y - __bfloat162float(__float2bfloat16(a.y));
            float rz = a.z - __bfloat162float(__float2bfloat16(a.z));
            float rw = a.w - __bfloat162float(__float2bfloat16(a.w));
            uint32_t l01 = pack_bf16hi(rx, ry);
            uint32_t l23 = pack_bf16hi(rz, rw);
            const int off = row * ASTR + (k4 << 1);
            *(ull*)(smem + A_HI + off) = (ull)h01 | ((ull)h23 << 32);
            *(ull*)(smem + A_LO + off) = (ull)l01 | ((ull)l23 << 32);
        }
        // --- stage B chunk [128k x 64n] hi/lo (no transpose; trans-ldsm) ---
        #pragma unroll 4
        for (int i = tid; i < KC*16; i += 128) {
            const int k  = i >> 4;
            const int n4 = (i & 15) << 2;
            float4 wv = *(const float4*)(W + (size_t)(k0 + k) * U_ + bn + n4);
            uint32_t h01 = pack_bf16hi(wv.x, wv.y);
            uint32_t h23 = pack_bf16hi(wv.z, wv.w);
            float rx = wv.x - __bfloat162float(__float2bfloat16(wv.x));
            float ry = wv.y - __bfloat162float(__float2bfloat16(wv.y));
            float rz = wv.z - __bfloat162float(__float2bfloat16(wv.z));
            float rw = wv.w - __bfloat162float(__float2bfloat16(wv.w));
            uint32_t l01 = pack_bf16hi(rx, ry);
            uint32_t l23 = pack_bf16hi(rz, rw);
            const int off = k * BSTR + (n4 << 1);
            *(ull*)(smem + BSM_HI + off) = (ull)h01 | ((ull)h23 << 32);
            *(ull*)(smem + BSM_LO + off) = (ull)l01 | ((ull)l23 << 32);
        }
        __syncthreads();

        // --- 8 k16-steps of MMAs ---
        #pragma unroll 2
        for (int s = 0; s < 8; s++) {
            uint32_t ah[2][4], al[2][4], bh[2][4], bl[2][4];
            const uint32_t as_ = aoff + (uint32_t)(s << 5);          // s*32B
            const uint32_t bs_ = boff + (uint32_t)(s * 16 * BSTR);
            ldsm_x4 (ah[0], smb + A_HI  + as_);
            ldsm_x4 (ah[1], smb + A_HI  + as_ + 16 * ASTR);
            ldsm_x4 (al[0], smb + A_LO  + as_);
            ldsm_x4 (al[1], smb + A_LO  + as_ + 16 * ASTR);
            ldsm_x4t(bh[0], smb + BSM_HI + bs_);
            ldsm_x4t(bh[1], smb + BSM_HI + bs_ + 32);
            ldsm_x4t(bl[0], smb + BSM_LO + bs_);
            ldsm_x4t(bl[1], smb + BSM_LO + bs_ + 32);
            #pragma unroll
            for (int mi = 0; mi < 2; mi++)
                #pragma unroll
                for (int p = 0; p < 2; p++) {
                    mma16816(acc[mi][2*p],   ah[mi], &bh[p][0]);
                    mma16816(acc[mi][2*p],   ah[mi], &bl[p][0]);
                    mma16816(acc[mi][2*p],   al[mi], &bh[p][0]);
                    mma16816(acc[mi][2*p+1], ah[mi], &bh[p][2]);
                    mma16816(acc[mi][2*p+1], ah[mi], &bl[p][2]);
                    mma16816(acc[mi][2*p+1], al[mi], &bh[p][2]);
                }
        }
    }

    // --- epilogue: bias + store fp32 ---
    #pragma unroll
    for (int mi = 0; mi < 2; mi++) {
        const int r = bm + mw*32 + mi*16 + (l >> 2);
        #pragma unroll
        for (int ni = 0; ni < 4; ni++) {
            const int c = bn + nw*32 + ni*8 + ((l & 3) << 1);
            float2 bb = *(const float2*)(bias + c);
            float2 o0 = make_float2(acc[mi][ni][0] + bb.x, acc[mi][ni][1] + bb.y);
            float2 o1 = make_float2(acc[mi][ni][2] + bb.x, acc[mi][ni][3] + bb.y);
            *(float2*)&C[(size_t)r * U_ + c]       = o0;
            *(float2*)&C[(size_t)(r + 8) * U_ + c] = o1;
        }
    }
}

// ========================================================================
// Fused attention (R9, unchanged): CTA = (b, 8-q tile), grid 256.
// ========================================================================
#define S2HSTRIDE 260
#define SM_S1   (64 * S2HSTRIDE)
#define SM_VW   (SM_S1 + QT * U_)
#define SM_SC   (SM_VW + U_)
#define SM_CBUF (SM_SC + QT * SV_)
#define SM_TOTAL_F (SM_CBUF + QT * 128 * 4)

__global__ __launch_bounds__(256, 2) void attn_kernel(
    const float* __restrict__ values, const float* __restrict__ Vw,
    float* __restrict__ out)
{
    extern __shared__ float sm[];
    float*  s2h  = sm;
    float*  s1s  = sm + SM_S1;
    float*  vws  = sm + SM_VW;
    float*  sc   = sm + SM_SC;
    float4* cbuf = (float4*)(sm + SM_CBUF);

    const int tid = threadIdx.x;
    const int b   = blockIdx.x >> 4;
    const int q0  = (blockIdx.x & 15) << 3;

    const float4* s1g4 = (const float4*)(g_s1 + ((size_t)b * SQ_ + q0) * U_);
    for (int i = tid; i < QT * (U_/4); i += 256)
        ((float4*)s1s)[i] = s1g4[i];
    if (tid < U_/4)
        ((float4*)vws)[tid] = ((const float4*)Vw)[tid];

    #pragma unroll 1
    for (int vh = 0; vh < 2; vh++) {
        const float4* s2g4 =
            (const float4*)(g_s2 + ((size_t)b * SV_ + (vh << 6)) * U_);
        for (int i = tid; i < 64 * (U_/4); i += 256) {
            int v = i >> 6, u4 = i & 63;
            *(float4*)&s2h[v * S2HSTRIDE + (u4 << 2)] = s2g4[i];
        }
        __syncthreads();

        const int v  = tid & 63;
        const int qg = tid >> 6;
        const float* s1q = s1s + (qg << 1) * U_;
        const float* s2r = s2h + v * S2HSTRIDE;
        float acc[2] = {0.f, 0.f};
        #pragma unroll 4
        for (int u = 0; u < U_; u += 4) {
            float4 f2 = *(const float4*)(s2r + u);
            float4 wv = *(const float4*)(vws + u);
            #pragma unroll
            for (int qi = 0; qi < 2; qi++) {
                float4 s1v = *(const float4*)(s1q + qi * U_ + u);
                acc[qi] += wv.x * tanh_fast(s1v.x + f2.x)
                         + wv.y * tanh_fast(s1v.y + f2.y)
                         + wv.z * tanh_fast(s1v.z + f2.z)
                         + wv.w * tanh_fast(s1v.w + f2.w);
            }
        }
        #pragma unroll
        for (int qi = 0; qi < 2; qi++)
            sc[((qg << 1) + qi) * SV_ + (vh << 6) + v] = acc[qi];
        __syncthreads();
    }

    {
        const int q = tid >> 5, lane = tid & 31;
        float x0 = sc[q*SV_ +      lane];
        float x1 = sc[q*SV_ + 32 + lane];
        float x2 = sc[q*SV_ + 64 + lane];
        float x3 = sc[q*SV_ + 96 + lane];
        float m = fmaxf(fmaxf(x0, x1), fmaxf(x2, x3));
        #pragma unroll
        for (int off = 16; off; off >>= 1)
            m = fmaxf(m, __shfl_xor_sync(0xffffffffu, m, off));
        float e0 = __expf(x0 - m), e1 = __expf(x1 - m);
        float e2 = __expf(x2 - m), e3 = __expf(x3 - m);
        float s = (e0 + e1) + (e2 + e3);
        #pragma unroll
        for (int off = 16; off; off >>= 1)
            s += __shfl_xor_sync(0xffffffffu, s, off);
        float inv = 1.0f / s;
        e0 *= inv; e1 *= inv; e2 *= inv; e3 *= inv;
        sc[q*SV_ +      lane] = e0;
        sc[q*SV_ + 32 + lane] = e1;
        sc[q*SV_ + 64 + lane] = e2;
        sc[q*SV_ + 96 + lane] = e3;
        float* wout = out + CTX_ELEMS + (size_t)(b * SQ_ + q0 + q) * SV_;
        wout[lane]      = e0;
        wout[32 + lane] = e1;
        wout[64 + lane] = e2;
        wout[96 + lane] = e3;
    }
    __syncthreads();

    {
        const int half = tid >> 7;
        const int dg   = tid & 127;
        float4 acc[QT];
        #pragma unroll
        for (int q = 0; q < QT; q++) acc[q] = make_float4(0.f, 0.f, 0.f, 0.f);

        const float* vb  = values + ((size_t)(b * SV_) + (half << 6)) * DV_ + (dg << 2);
        const float* scv = sc + (half << 6);
        #pragma unroll 4
        for (int vv = 0; vv < 64; vv++) {
            float4 val = *(const float4*)(vb + (size_t)vv * DV_);
            #pragma unroll
            for (int q = 0; q < QT; q++) {
                float wq = scv[q * SV_ + vv];
                acc[q].x += wq * val.x;
                acc[q].y += wq * val.y;
                acc[q].z += wq * val.z;
                acc[q].w += wq * val.w;
            }
        }
        if (half) {
            #pragma unroll
            for (int q = 0; q < QT; q++) cbuf[q * 128 + dg] = acc[q];
        }
        __syncthreads();
        if (!half) {
            #pragma unroll
            for (int q = 0; q < QT; q++) {
                float4 o = cbuf[q * 128 + dg];
                o.x += acc[q].x; o.y += acc[q].y;
                o.z += acc[q].z; o.w += acc[q].w;
                *(float4*)&out[(size_t)(b * SQ_ + q0 + q) * DV_ + (dg << 2)] = o;
            }
        }
    }
}

// ========================================================================
extern "C" void kernel_launch(void* const* d_in, const int* in_sizes, int n_in,
                              void* d_out, int out_size)
{
    const float* query  = (const float*)d_in[0];
    const float* values = (const float*)d_in[1];
    const float* W1     = (const float*)d_in[2];
    const float* b1     = (const float*)d_in[3];
    const float* W2     = (const float*)d_in[4];
    const float* b2     = (const float*)d_in[5];
    const float* Vw     = (const float*)d_in[6];
    // d_in[7] = Vb: softmax shift-invariance -> provably cancels. Unused.
    float* out = (float*)d_out;

    cudaFuncSetAttribute(gemm_tc_kernel,
                         cudaFuncAttributeMaxDynamicSharedMemorySize,
                         SM_GEMM_TOTAL);
    dim3 gemm_grid(U_/64, (B_*SQ_)/64, 2);      // 4 x 32 x 2 = 256 CTAs
    gemm_tc_kernel<<<gemm_grid, 128, SM_GEMM_TOTAL>>>(
        query, values, W1, b1, W2, b2);

    const size_t attn_smem = (size_t)SM_TOTAL_F * sizeof(float);
    cudaFuncSetAttribute(attn_kernel,
                         cudaFuncAttributeMaxDynamicSharedMemorySize,
                         (int)attn_smem);
    attn_kernel<<<B_ * (SQ_/QT), 256, attn_smem>>>(values, Vw, out);
}

// round 13
// speedup vs baseline: 1.4346x; 1.0520x over previous
#include <cuda_runtime.h>
#include <cuda_bf16.h>
#include <math.h>
#include <cstdint>

#define B_   16
#define SQ_  128
#define SV_  128
#define DQ_  512
#define DV_  512
#define U_   256
#define QT   8
#define CTX_ELEMS (B_*SQ_*DV_)

typedef unsigned long long ull;

// Scratch (allocation-free rule: __device__ globals)
__device__ float g_s1[B_*SQ_*U_];    // [b][q][u]
__device__ float g_s2[B_*SV_*U_];    // [b][v][u]
// Pre-converted split-bf16 operands
__device__ __nv_bfloat16 g_ah[2][B_*SQ_*DQ_];  // [which][m][k] hi
__device__ __nv_bfloat16 g_al[2][B_*SQ_*DQ_];  // lo
__device__ __nv_bfloat16 g_wh[2][DQ_*U_];      // [which][k][n] hi
__device__ __nv_bfloat16 g_wl[2][DQ_*U_];      // lo

__device__ __forceinline__ float tanh_fast(float x) {
    float y;
    asm("tanh.approx.f32 %0, %1;" : "=f"(y) : "f"(x));
    return y;
}
__device__ __forceinline__ uint32_t smem_u32(const void* p) {
    uint32_t a;
    asm("{ .reg .u64 t; cvta.to.shared.u64 t, %1; cvt.u32.u64 %0, t; }"
        : "=r"(a) : "l"(p));
    return a;
}
__device__ __forceinline__ void ldsm_x4(uint32_t* r, uint32_t addr) {
    asm volatile("ldmatrix.sync.aligned.m8n8.x4.shared.b16 {%0,%1,%2,%3}, [%4];"
        : "=r"(r[0]), "=r"(r[1]), "=r"(r[2]), "=r"(r[3]) : "r"(addr));
}
__device__ __forceinline__ void ldsm_x4t(uint32_t* r, uint32_t addr) {
    asm volatile("ldmatrix.sync.aligned.m8n8.x4.trans.shared.b16 {%0,%1,%2,%3}, [%4];"
        : "=r"(r[0]), "=r"(r[1]), "=r"(r[2]), "=r"(r[3]) : "r"(addr));
}
__device__ __forceinline__ void mma16816(float* c, const uint32_t* a,
                                         const uint32_t* b) {
    asm volatile(
        "mma.sync.aligned.m16n8k16.row.col.f32.bf16.bf16.f32 "
        "{%0,%1,%2,%3}, {%4,%5,%6,%7}, {%8,%9}, {%0,%1,%2,%3};"
        : "+f"(c[0]), "+f"(c[1]), "+f"(c[2]), "+f"(c[3])
        : "r"(a[0]), "r"(a[1]), "r"(a[2]), "r"(a[3]), "r"(b[0]), "r"(b[1]));
}
__device__ __forceinline__ ull split_pack(float4 a, ull& lp) {
    __nv_bfloat16 h0 = __float2bfloat16(a.x);
    __nv_bfloat16 h1 = __float2bfloat16(a.y);
    __nv_bfloat16 h2 = __float2bfloat16(a.z);
    __nv_bfloat16 h3 = __float2bfloat16(a.w);
    __nv_bfloat16 l0 = __float2bfloat16(a.x - __bfloat162float(h0));
    __nv_bfloat16 l1 = __float2bfloat16(a.y - __bfloat162float(h1));
    __nv_bfloat16 l2 = __float2bfloat16(a.z - __bfloat162float(h2));
    __nv_bfloat16 l3 = __float2bfloat16(a.w - __bfloat162float(h3));
    lp = (ull)__bfloat16_as_ushort(l0) | ((ull)__bfloat16_as_ushort(l1) << 16)
       | ((ull)__bfloat16_as_ushort(l2) << 32) | ((ull)__bfloat16_as_ushort(l3) << 48);
    return (ull)__bfloat16_as_ushort(h0) | ((ull)__bfloat16_as_ushort(h1) << 16)
         | ((ull)__bfloat16_as_ushort(h2) << 32) | ((ull)__bfloat16_as_ushort(h3) << 48);
}

// ========================================================================
// Pre-convert fp32 -> split bf16 (hi/lo), once, to global.
// blockIdx.y: 0=query, 1=values, 2=W1, 3=W2.
// ========================================================================
__global__ __launch_bounds__(256) void preconv_kernel(
    const float* __restrict__ q, const float* __restrict__ v,
    const float* __restrict__ w1, const float* __restrict__ w2)
{
    const int z = blockIdx.y;
    const float* src = (z == 0) ? q : (z == 1) ? v : (z == 2) ? w1 : w2;
    __nv_bfloat16* dh = (z < 2) ? g_ah[z] : g_wh[z - 2];
    __nv_bfloat16* dl = (z < 2) ? g_al[z] : g_wl[z - 2];
    const int n4 = (z < 2) ? (B_*SQ_*DQ_/4) : (DQ_*U_/4);

    for (int i = blockIdx.x * 256 + threadIdx.x; i < n4; i += gridDim.x * 256) {
        float4 a = ((const float4*)src)[i];
        ull lp, hp = split_pack(a, lp);
        ((ull*)dh)[i] = hp;
        ((ull*)dl)[i] = lp;
    }
}

// ========================================================================
// Tensor-core dual GEMM from pre-converted bf16 (single wave):
// CTA tile 128x64, 256 threads (8 warps: 4m x 2n, 32x32 warp tiles),
// K in 4 chunks of 128. D = Ah*Bh + Ah*Bl + Al*Bh (fp32 accum).
// grid (4, 16, 2) = 128 CTAs.
// ========================================================================
#define KC    128
#define ASTR  272                          // 128 bf16 = 256B + 16 pad
#define BSTR  144                          // 64 bf16 = 128B + 16 pad
#define A_HI  0
#define A_LO  (128 * ASTR)                 // 34816
#define BSM_HI (2 * 128 * ASTR)            // 69632
#define BSM_LO (BSM_HI + KC * BSTR)        // 88064
#define SM_GEMM_TOTAL (BSM_LO + KC * BSTR) // 106496 B

__global__ __launch_bounds__(256) void gemm_tc_kernel(
    const float* __restrict__ b1, const float* __restrict__ b2)
{
    extern __shared__ char smem[];
    const uint32_t smb = smem_u32(smem);
    const int tid = threadIdx.x;
    const int l   = tid & 31;
    const int w   = tid >> 5;
    const int mw  = w >> 1;            // 0..3 -> warp rows mw*32
    const int nw  = w & 1;             // 0..1 -> warp cols nw*32

    const int which = blockIdx.z;
    const __nv_bfloat16* __restrict__ Ah = g_ah[which];
    const __nv_bfloat16* __restrict__ Al = g_al[which];
    const __nv_bfloat16* __restrict__ Wh = g_wh[which];
    const __nv_bfloat16* __restrict__ Wl = g_wl[which];
    const float* __restrict__ bias = which ? b2 : b1;
    float* __restrict__ C          = which ? g_s2 : g_s1;

    const int bm = blockIdx.y * 128;
    const int bn = blockIdx.x * 64;

    float acc[2][4][4];
    #pragma unroll
    for (int mi = 0; mi < 2; mi++)
        #pragma unroll
        for (int ni = 0; ni < 4; ni++)
            #pragma unroll
            for (int j = 0; j < 4; j++) acc[mi][ni][j] = 0.f;

    // ldmatrix per-lane base addresses (fragment logic identical to R12)
    const int arow = mw*32 + (l & 7) + 8*((l >> 3) & 1);
    const uint32_t aoff = (uint32_t)(arow * ASTR + ((l >> 4) << 4));
    const int brow = (l & 7) + 8*((l >> 3) & 1);
    const uint32_t boff = (uint32_t)(brow * BSTR + nw*64 + ((l >> 4) << 4));

    #pragma unroll 1
    for (int ch = 0; ch < 4; ch++) {
        const int k0 = ch * KC;
        __syncthreads();   // smem reuse barrier

        // --- stage A chunk [128m x 128k] hi/lo (pure bf16 copies) ---
        #pragma unroll 4
        for (int i = tid; i < 128 * 16; i += 256) {
            const int row = i >> 4;
            const int kc  = (i & 15) << 3;           // 8 bf16
            const size_t gidx = (size_t)(bm + row) * DQ_ + k0 + kc;
            uint4 h = *(const uint4*)(Ah + gidx);
            uint4 lo = *(const uint4*)(Al + gidx);
            const int off = row * ASTR + (kc << 1);
            *(uint4*)(smem + A_HI + off) = h;
            *(uint4*)(smem + A_LO + off) = lo;
        }
        // --- stage B chunk [128k x 64n] hi/lo ---
        #pragma unroll 4
        for (int i = tid; i < KC * 8; i += 256) {
            const int k  = i >> 3;
            const int nc = (i & 7) << 3;             // 8 bf16
            const size_t gidx = (size_t)(k0 + k) * U_ + bn + nc;
            uint4 h = *(const uint4*)(Wh + gidx);
            uint4 lo = *(const uint4*)(Wl + gidx);
            const int off = k * BSTR + (nc << 1);
            *(uint4*)(smem + BSM_HI + off) = h;
            *(uint4*)(smem + BSM_LO + off) = lo;
        }
        __syncthreads();

        // --- 8 k16-steps of MMAs ---
        #pragma unroll 2
        for (int s = 0; s < 8; s++) {
            uint32_t ah[2][4], al[2][4], bh[2][4], bl[2][4];
            const uint32_t as_ = aoff + (uint32_t)(s << 5);          // s*32B
            const uint32_t bs_ = boff + (uint32_t)(s * 16 * BSTR);
            ldsm_x4 (ah[0], smb + A_HI  + as_);
            ldsm_x4 (ah[1], smb + A_HI  + as_ + 16 * ASTR);
            ldsm_x4 (al[0], smb + A_LO  + as_);
            ldsm_x4 (al[1], smb + A_LO  + as_ + 16 * ASTR);
            ldsm_x4t(bh[0], smb + BSM_HI + bs_);
            ldsm_x4t(bh[1], smb + BSM_HI + bs_ + 32);
            ldsm_x4t(bl[0], smb + BSM_LO + bs_);
            ldsm_x4t(bl[1], smb + BSM_LO + bs_ + 32);
            #pragma unroll
            for (int mi = 0; mi < 2; mi++)
                #pragma unroll
                for (int p = 0; p < 2; p++) {
                    mma16816(acc[mi][2*p],   ah[mi], &bh[p][0]);
                    mma16816(acc[mi][2*p],   ah[mi], &bl[p][0]);
                    mma16816(acc[mi][2*p],   al[mi], &bh[p][0]);
                    mma16816(acc[mi][2*p+1], ah[mi], &bh[p][2]);
                    mma16816(acc[mi][2*p+1], ah[mi], &bl[p][2]);
                    mma16816(acc[mi][2*p+1], al[mi], &bh[p][2]);
                }
        }
    }

    // --- epilogue: bias + store fp32 ---
    #pragma unroll
    for (int mi = 0; mi < 2; mi++) {
        const int r = bm + mw*32 + mi*16 + (l >> 2);
        #pragma unroll
        for (int ni = 0; ni < 4; ni++) {
            const int c = bn + nw*32 + ni*8 + ((l & 3) << 1);
            float2 bb = *(const float2*)(bias + c);
            float2 o0 = make_float2(acc[mi][ni][0] + bb.x, acc[mi][ni][1] + bb.y);
            float2 o1 = make_float2(acc[mi][ni][2] + bb.x, acc[mi][ni][3] + bb.y);
            *(float2*)&C[(size_t)r * U_ + c]       = o0;
            *(float2*)&C[(size_t)(r + 8) * U_ + c] = o1;
        }
    }
}

// ========================================================================
// Fused attention (R12, unchanged): CTA = (b, 8-q tile), grid 256.
// ========================================================================
#define S2HSTRIDE 260
#define SM_S1   (64 * S2HSTRIDE)
#define SM_VW   (SM_S1 + QT * U_)
#define SM_SC   (SM_VW + U_)
#define SM_CBUF (SM_SC + QT * SV_)
#define SM_TOTAL_F (SM_CBUF + QT * 128 * 4)

__global__ __launch_bounds__(256, 2) void attn_kernel(
    const float* __restrict__ values, const float* __restrict__ Vw,
    float* __restrict__ out)
{
    extern __shared__ float sm[];
    float*  s2h  = sm;
    float*  s1s  = sm + SM_S1;
    float*  vws  = sm + SM_VW;
    float*  sc   = sm + SM_SC;
    float4* cbuf = (float4*)(sm + SM_CBUF);

    const int tid = threadIdx.x;
    const int b   = blockIdx.x >> 4;
    const int q0  = (blockIdx.x & 15) << 3;

    const float4* s1g4 = (const float4*)(g_s1 + ((size_t)b * SQ_ + q0) * U_);
    for (int i = tid; i < QT * (U_/4); i += 256)
        ((float4*)s1s)[i] = s1g4[i];
    if (tid < U_/4)
        ((float4*)vws)[tid] = ((const float4*)Vw)[tid];

    #pragma unroll 1
    for (int vh = 0; vh < 2; vh++) {
        const float4* s2g4 =
            (const float4*)(g_s2 + ((size_t)b * SV_ + (vh << 6)) * U_);
        for (int i = tid; i < 64 * (U_/4); i += 256) {
            int v = i >> 6, u4 = i & 63;
            *(float4*)&s2h[v * S2HSTRIDE + (u4 << 2)] = s2g4[i];
        }
        __syncthreads();

        const int v  = tid & 63;
        const int qg = tid >> 6;
        const float* s1q = s1s + (qg << 1) * U_;
        const float* s2r = s2h + v * S2HSTRIDE;
        float acc[2] = {0.f, 0.f};
        #pragma unroll 4
        for (int u = 0; u < U_; u += 4) {
            float4 f2 = *(const float4*)(s2r + u);
            float4 wv = *(const float4*)(vws + u);
            #pragma unroll
            for (int qi = 0; qi < 2; qi++) {
                float4 s1v = *(const float4*)(s1q + qi * U_ + u);
                acc[qi] += wv.x * tanh_fast(s1v.x + f2.x)
                         + wv.y * tanh_fast(s1v.y + f2.y)
                         + wv.z * tanh_fast(s1v.z + f2.z)
                         + wv.w * tanh_fast(s1v.w + f2.w);
            }
        }
        #pragma unroll
        for (int qi = 0; qi < 2; qi++)
            sc[((qg << 1) + qi) * SV_ + (vh << 6) + v] = acc[qi];
        __syncthreads();
    }

    {
        const int q = tid >> 5, lane = tid & 31;
        float x0 = sc[q*SV_ +      lane];
        float x1 = sc[q*SV_ + 32 + lane];
        float x2 = sc[q*SV_ + 64 + lane];
        float x3 = sc[q*SV_ + 96 + lane];
        float m = fmaxf(fmaxf(x0, x1), fmaxf(x2, x3));
        #pragma unroll
        for (int off = 16; off; off >>= 1)
            m = fmaxf(m, __shfl_xor_sync(0xffffffffu, m, off));
        float e0 = __expf(x0 - m), e1 = __expf(x1 - m);
        float e2 = __expf(x2 - m), e3 = __expf(x3 - m);
        float s = (e0 + e1) + (e2 + e3);
        #pragma unroll
        for (int off = 16; off; off >>= 1)
            s += __shfl_xor_sync(0xffffffffu, s, off);
        float inv = 1.0f / s;
        e0 *= inv; e1 *= inv; e2 *= inv; e3 *= inv;
        sc[q*SV_ +      lane] = e0;
        sc[q*SV_ + 32 + lane] = e1;
        sc[q*SV_ + 64 + lane] = e2;
        sc[q*SV_ + 96 + lane] = e3;
        float* wout = out + CTX_ELEMS + (size_t)(b * SQ_ + q0 + q) * SV_;
        wout[lane]      = e0;
        wout[32 + lane] = e1;
        wout[64 + lane] = e2;
        wout[96 + lane] = e3;
    }
    __syncthreads();

    {
        const int half = tid >> 7;
        const int dg   = tid & 127;
        float4 acc[QT];
        #pragma unroll
        for (int q = 0; q < QT; q++) acc[q] = make_float4(0.f, 0.f, 0.f, 0.f);

        const float* vb  = values + ((size_t)(b * SV_) + (half << 6)) * DV_ + (dg << 2);
        const float* scv = sc + (half << 6);
        #pragma unroll 4
        for (int vv = 0; vv < 64; vv++) {
            float4 val = *(const float4*)(vb + (size_t)vv * DV_);
            #pragma unroll
            for (int q = 0; q < QT; q++) {
                float wq = scv[q * SV_ + vv];
                acc[q].x += wq * val.x;
                acc[q].y += wq * val.y;
                acc[q].z += wq * val.z;
                acc[q].w += wq * val.w;
            }
        }
        if (half) {
            #pragma unroll
            for (int q = 0; q < QT; q++) cbuf[q * 128 + dg] = acc[q];
        }
        __syncthreads();
        if (!half) {
            #pragma unroll
            for (int q = 0; q < QT; q++) {
                float4 o = cbuf[q * 128 + dg];
                o.x += acc[q].x; o.y += acc[q].y;
                o.z += acc[q].z; o.w += acc[q].w;
                *(float4*)&out[(size_t)(b * SQ_ + q0 + q) * DV_ + (dg << 2)] = o;
            }
        }
    }
}

// ========================================================================
extern "C" void kernel_launch(void* const* d_in, const int* in_sizes, int n_in,
                              void* d_out, int out_size)
{
    const float* query  = (const float*)d_in[0];
    const float* values = (const float*)d_in[1];
    const float* W1     = (const float*)d_in[2];
    const float* b1     = (const float*)d_in[3];
    const float* W2     = (const float*)d_in[4];
    const float* b2     = (const float*)d_in[5];
    const float* Vw     = (const float*)d_in[6];
    // d_in[7] = Vb: softmax shift-invariance -> provably cancels. Unused.
    float* out = (float*)d_out;

    dim3 pc_grid(148, 4);
    preconv_kernel<<<pc_grid, 256>>>(query, values, W1, W2);

    cudaFuncSetAttribute(gemm_tc_kernel,
                         cudaFuncAttributeMaxDynamicSharedMemorySize,
                         SM_GEMM_TOTAL);
    dim3 gemm_grid(U_/64, (B_*SQ_)/128, 2);      // 4 x 16 x 2 = 128 CTAs
    gemm_tc_kernel<<<gemm_grid, 256, SM_GEMM_TOTAL>>>(b1, b2);

    const size_t attn_smem = (size_t)SM_TOTAL_F * sizeof(float);
    cudaFuncSetAttribute(attn_kernel,
                         cudaFuncAttributeMaxDynamicSharedMemorySize,
                         (int)attn_smem);
    attn_kernel<<<B_ * (SQ_/QT), 256, attn_smem>>>(values, Vw, out);
}

// round 14
// speedup vs baseline: 1.5545x; 1.0835x over previous
#include <cuda_runtime.h>
#include <cuda_bf16.h>
#include <math.h>
#include <cstdint>

#define B_   16
#define SQ_  128
#define SV_  128
#define DQ_  512
#define DV_  512
#define U_   256
#define QT   8
#define CTX_ELEMS (B_*SQ_*DV_)

typedef unsigned long long ull;

// Scratch (allocation-free rule: __device__ globals)
__device__ float g_s1[B_*SQ_*U_];    // [b][q][u]
__device__ float g_s2[B_*SV_*U_];    // [b][v][u]
// Pre-converted split-bf16 operands
__device__ __nv_bfloat16 g_ah[2][B_*SQ_*DQ_];  // [which][m][k] hi
__device__ __nv_bfloat16 g_al[2][B_*SQ_*DQ_];  // lo
__device__ __nv_bfloat16 g_wh[2][DQ_*U_];      // [which][k][n] hi
__device__ __nv_bfloat16 g_wl[2][DQ_*U_];      // lo

__device__ __forceinline__ float tanh_fast(float x) {
    float y;
    asm("tanh.approx.f32 %0, %1;" : "=f"(y) : "f"(x));
    return y;
}
__device__ __forceinline__ uint32_t smem_u32(const void* p) {
    uint32_t a;
    asm("{ .reg .u64 t; cvta.to.shared.u64 t, %1; cvt.u32.u64 %0, t; }"
        : "=r"(a) : "l"(p));
    return a;
}
__device__ __forceinline__ void ldsm_x4(uint32_t* r, uint32_t addr) {
    asm volatile("ldmatrix.sync.aligned.m8n8.x4.shared.b16 {%0,%1,%2,%3}, [%4];"
        : "=r"(r[0]), "=r"(r[1]), "=r"(r[2]), "=r"(r[3]) : "r"(addr));
}
__device__ __forceinline__ void ldsm_x4t(uint32_t* r, uint32_t addr) {
    asm volatile("ldmatrix.sync.aligned.m8n8.x4.trans.shared.b16 {%0,%1,%2,%3}, [%4];"
        : "=r"(r[0]), "=r"(r[1]), "=r"(r[2]), "=r"(r[3]) : "r"(addr));
}
__device__ __forceinline__ void mma16816(float* c, const uint32_t* a,
                                         const uint32_t* b) {
    asm volatile(
        "mma.sync.aligned.m16n8k16.row.col.f32.bf16.bf16.f32 "
        "{%0,%1,%2,%3}, {%4,%5,%6,%7}, {%8,%9}, {%0,%1,%2,%3};"
        : "+f"(c[0]), "+f"(c[1]), "+f"(c[2]), "+f"(c[3])
        : "r"(a[0]), "r"(a[1]), "r"(a[2]), "r"(a[3]), "r"(b[0]), "r"(b[1]));
}
__device__ __forceinline__ ull split_pack(float4 a, ull& lp) {
    __nv_bfloat16 h0 = __float2bfloat16(a.x);
    __nv_bfloat16 h1 = __float2bfloat16(a.y);
    __nv_bfloat16 h2 = __float2bfloat16(a.z);
    __nv_bfloat16 h3 = __float2bfloat16(a.w);
    __nv_bfloat16 l0 = __float2bfloat16(a.x - __bfloat162float(h0));
    __nv_bfloat16 l1 = __float2bfloat16(a.y - __bfloat162float(h1));
    __nv_bfloat16 l2 = __float2bfloat16(a.z - __bfloat162float(h2));
    __nv_bfloat16 l3 = __float2bfloat16(a.w - __bfloat162float(h3));
    lp = (ull)__bfloat16_as_ushort(l0) | ((ull)__bfloat16_as_ushort(l1) << 16)
       | ((ull)__bfloat16_as_ushort(l2) << 32) | ((ull)__bfloat16_as_ushort(l3) << 48);
    return (ull)__bfloat16_as_ushort(h0) | ((ull)__bfloat16_as_ushort(h1) << 16)
         | ((ull)__bfloat16_as_ushort(h2) << 32) | ((ull)__bfloat16_as_ushort(h3) << 48);
}

// ========================================================================
// Pre-convert fp32 -> split bf16 (hi/lo), once, to global.
// blockIdx.y: 0=query, 1=values, 2=W1, 3=W2.  grid.x=256 so the big
// arrays give exactly 4 grid-stride iterations; LDGs batched for MLP=4.
// ========================================================================
__global__ __launch_bounds__(256) void preconv_kernel(
    const float* __restrict__ q, const float* __restrict__ v,
    const float* __restrict__ w1, const float* __restrict__ w2)
{
    const int z = blockIdx.y;
    const float* src = (z == 0) ? q : (z == 1) ? v : (z == 2) ? w1 : w2;
    __nv_bfloat16* dh = (z < 2) ? g_ah[z] : g_wh[z - 2];
    __nv_bfloat16* dl = (z < 2) ? g_al[z] : g_wl[z - 2];
    const int n4 = (z < 2) ? (B_*SQ_*DQ_/4) : (DQ_*U_/4);

    const int stride = gridDim.x * 256;            // 65536
    int i = blockIdx.x * 256 + threadIdx.x;

    for (; i + 3 * stride < n4; i += 4 * stride) {
        float4 a0 = ((const float4*)src)[i];
        float4 a1 = ((const float4*)src)[i +     stride];
        float4 a2 = ((const float4*)src)[i + 2 * stride];
        float4 a3 = ((const float4*)src)[i + 3 * stride];
        ull l0, h0 = split_pack(a0, l0);
        ull l1, h1 = split_pack(a1, l1);
        ull l2, h2 = split_pack(a2, l2);
        ull l3, h3 = split_pack(a3, l3);
        ((ull*)dh)[i]              = h0;  ((ull*)dl)[i]              = l0;
        ((ull*)dh)[i +     stride] = h1;  ((ull*)dl)[i +     stride] = l1;
        ((ull*)dh)[i + 2 * stride] = h2;  ((ull*)dl)[i + 2 * stride] = l2;
        ((ull*)dh)[i + 3 * stride] = h3;  ((ull*)dl)[i + 3 * stride] = l3;
    }
    for (; i < n4; i += stride) {
        float4 a = ((const float4*)src)[i];
        ull lp, hp = split_pack(a, lp);
        ((ull*)dh)[i] = hp;
        ((ull*)dl)[i] = lp;
    }
}

// ========================================================================
// Tensor-core dual GEMM, register-prefetch pipelined:
// CTA tile 128x64, 256 threads (8 warps: 4m x 2n), K in 4 chunks of 128.
// Chunk ch+1's LDGs issue before chunk ch's MMA loop (latency hidden).
// D = Ah*Bh + Ah*Bl + Al*Bh (fp32 accum). grid (4,16,2) = 128 CTAs.
// ========================================================================
#define KC    128
#define ASTR  272
#define BSTR  144
#define A_HI  0
#define A_LO  (128 * ASTR)                 // 34816
#define BSM_HI (2 * 128 * ASTR)            // 69632
#define BSM_LO (BSM_HI + KC * BSTR)        // 88064
#define SM_GEMM_TOTAL (BSM_LO + KC * BSTR) // 106496 B

__global__ __launch_bounds__(256, 1) void gemm_tc_kernel(
    const float* __restrict__ b1, const float* __restrict__ b2)
{
    extern __shared__ char smem[];
    const uint32_t smb = smem_u32(smem);
    const int tid = threadIdx.x;
    const int l   = tid & 31;
    const int w   = tid >> 5;
    const int mw  = w >> 1;
    const int nw  = w & 1;

    const int which = blockIdx.z;
    const __nv_bfloat16* __restrict__ Ah = g_ah[which];
    const __nv_bfloat16* __restrict__ Al = g_al[which];
    const __nv_bfloat16* __restrict__ Wh = g_wh[which];
    const __nv_bfloat16* __restrict__ Wl = g_wl[which];
    const float* __restrict__ bias = which ? b2 : b1;
    float* __restrict__ C          = which ? g_s2 : g_s1;

    const int bm = blockIdx.y * 128;
    const int bn = blockIdx.x * 64;

    float acc[2][4][4];
    #pragma unroll
    for (int mi = 0; mi < 2; mi++)
        #pragma unroll
        for (int ni = 0; ni < 4; ni++)
            #pragma unroll
            for (int j = 0; j < 4; j++) acc[mi][ni][j] = 0.f;

    // per-thread staging coordinates (fixed across chunks)
    const int a_row = tid >> 4;                 // 0..15 (i = tid + j*256: row = i>>4)
    // NOTE: for j-th iteration, i = tid + j*256 -> row = a_row + j*16, kc fixed
    const int a_kc  = (tid & 15) << 3;
    const int b_k   = tid >> 3;                 // + j*32
    const int b_nc  = (tid & 7) << 3;

    uint4 pa_h[8], pa_l[8], pb_h[4], pb_l[4];

    // ldmatrix per-lane base addresses (fragment logic identical to R12)
    const int arow = mw*32 + (l & 7) + 8*((l >> 3) & 1);
    const uint32_t aoff = (uint32_t)(arow * ASTR + ((l >> 4) << 4));
    const int brow = (l & 7) + 8*((l >> 3) & 1);
    const uint32_t boff = (uint32_t)(brow * BSTR + nw*64 + ((l >> 4) << 4));

    // prologue: load chunk 0 into registers
    #pragma unroll
    for (int j = 0; j < 8; j++) {
        const size_t g = (size_t)(bm + a_row + j*16) * DQ_ + a_kc;
        pa_h[j] = *(const uint4*)(Ah + g);
        pa_l[j] = *(const uint4*)(Al + g);
    }
    #pragma unroll
    for (int j = 0; j < 4; j++) {
        const size_t g = (size_t)(b_k + j*32) * U_ + bn + b_nc;
        pb_h[j] = *(const uint4*)(Wh + g);
        pb_l[j] = *(const uint4*)(Wl + g);
    }

    #pragma unroll 1
    for (int ch = 0; ch < 4; ch++) {
        __syncthreads();   // smem free from previous chunk's MMAs

        // store prefetched chunk to smem
        #pragma unroll
        for (int j = 0; j < 8; j++) {
            const int off = (a_row + j*16) * ASTR + (a_kc << 1);
            *(uint4*)(smem + A_HI + off) = pa_h[j];
            *(uint4*)(smem + A_LO + off) = pa_l[j];
        }
        #pragma unroll
        for (int j = 0; j < 4; j++) {
            const int off = (b_k + j*32) * BSTR + (b_nc << 1);
            *(uint4*)(smem + BSM_HI + off) = pb_h[j];
            *(uint4*)(smem + BSM_LO + off) = pb_l[j];
        }
        __syncthreads();

        // issue next chunk's LDGs (consumed after next barrier)
        if (ch < 3) {
            const int k0 = (ch + 1) * KC;
            #pragma unroll
            for (int j = 0; j < 8; j++) {
                const size_t g = (size_t)(bm + a_row + j*16) * DQ_ + k0 + a_kc;
                pa_h[j] = *(const uint4*)(Ah + g);
                pa_l[j] = *(const uint4*)(Al + g);
            }
            #pragma unroll
            for (int j = 0; j < 4; j++) {
                const size_t g = (size_t)(k0 + b_k + j*32) * U_ + bn + b_nc;
                pb_h[j] = *(const uint4*)(Wh + g);
                pb_l[j] = *(const uint4*)(Wl + g);
            }
        }

        // --- 8 k16-steps of MMAs on the staged chunk ---
        #pragma unroll 2
        for (int s = 0; s < 8; s++) {
            uint32_t ah[2][4], al[2][4], bh[2][4], bl[2][4];
            const uint32_t as_ = aoff + (uint32_t)(s << 5);
            const uint32_t bs_ = boff + (uint32_t)(s * 16 * BSTR);
            ldsm_x4 (ah[0], smb + A_HI  + as_);
            ldsm_x4 (ah[1], smb + A_HI  + as_ + 16 * ASTR);
            ldsm_x4 (al[0], smb + A_LO  + as_);
            ldsm_x4 (al[1], smb + A_LO  + as_ + 16 * ASTR);
            ldsm_x4t(bh[0], smb + BSM_HI + bs_);
            ldsm_x4t(bh[1], smb + BSM_HI + bs_ + 32);
            ldsm_x4t(bl[0], smb + BSM_LO + bs_);
            ldsm_x4t(bl[1], smb + BSM_LO + bs_ + 32);
            #pragma unroll
            for (int mi = 0; mi < 2; mi++)
                #pragma unroll
                for (int p = 0; p < 2; p++) {
                    mma16816(acc[mi][2*p],   ah[mi], &bh[p][0]);
                    mma16816(acc[mi][2*p],   ah[mi], &bl[p][0]);
                    mma16816(acc[mi][2*p],   al[mi], &bh[p][0]);
                    mma16816(acc[mi][2*p+1], ah[mi], &bh[p][2]);
                    mma16816(acc[mi][2*p+1], ah[mi], &bl[p][2]);
                    mma16816(acc[mi][2*p+1], al[mi], &bh[p][2]);
                }
        }
    }

    // --- epilogue: bias + store fp32 ---
    #pragma unroll
    for (int mi = 0; mi < 2; mi++) {
        const int r = bm + mw*32 + mi*16 + (l >> 2);
        #pragma unroll
        for (int ni = 0; ni < 4; ni++) {
            const int c = bn + nw*32 + ni*8 + ((l & 3) << 1);
            float2 bb = *(const float2*)(bias + c);
            float2 o0 = make_float2(acc[mi][ni][0] + bb.x, acc[mi][ni][1] + bb.y);
            float2 o1 = make_float2(acc[mi][ni][2] + bb.x, acc[mi][ni][3] + bb.y);
            *(float2*)&C[(size_t)r * U_ + c]       = o0;
            *(float2*)&C[(size_t)(r + 8) * U_ + c] = o1;
        }
    }
}

// ========================================================================
// Fused attention (R12/R13, unchanged): CTA = (b, 8-q tile), grid 256.
// ========================================================================
#define S2HSTRIDE 260
#define SM_S1   (64 * S2HSTRIDE)
#define SM_VW   (SM_S1 + QT * U_)
#define SM_SC   (SM_VW + U_)
#define SM_CBUF (SM_SC + QT * SV_)
#define SM_TOTAL_F (SM_CBUF + QT * 128 * 4)

__global__ __launch_bounds__(256, 2) void attn_kernel(
    const float* __restrict__ values, const float* __restrict__ Vw,
    float* __restrict__ out)
{
    extern __shared__ float sm[];
    float*  s2h  = sm;
    float*  s1s  = sm + SM_S1;
    float*  vws  = sm + SM_VW;
    float*  sc   = sm + SM_SC;
    float4* cbuf = (float4*)(sm + SM_CBUF);

    const int tid = threadIdx.x;
    const int b   = blockIdx.x >> 4;
    const int q0  = (blockIdx.x & 15) << 3;

    const float4* s1g4 = (const float4*)(g_s1 + ((size_t)b * SQ_ + q0) * U_);
    for (int i = tid; i < QT * (U_/4); i += 256)
        ((float4*)s1s)[i] = s1g4[i];
    if (tid < U_/4)
        ((float4*)vws)[tid] = ((const float4*)Vw)[tid];

    #pragma unroll 1
    for (int vh = 0; vh < 2; vh++) {
        const float4* s2g4 =
            (const float4*)(g_s2 + ((size_t)b * SV_ + (vh << 6)) * U_);
        for (int i = tid; i < 64 * (U_/4); i += 256) {
            int v = i >> 6, u4 = i & 63;
            *(float4*)&s2h[v * S2HSTRIDE + (u4 << 2)] = s2g4[i];
        }
        __syncthreads();

        const int v  = tid & 63;
        const int qg = tid >> 6;
        const float* s1q = s1s + (qg << 1) * U_;
        const float* s2r = s2h + v * S2HSTRIDE;
        float acc[2] = {0.f, 0.f};
        #pragma unroll 4
        for (int u = 0; u < U_; u += 4) {
            float4 f2 = *(const float4*)(s2r + u);
            float4 wv = *(const float4*)(vws + u);
            #pragma unroll
            for (int qi = 0; qi < 2; qi++) {
                float4 s1v = *(const float4*)(s1q + qi * U_ + u);
                acc[qi] += wv.x * tanh_fast(s1v.x + f2.x)
                         + wv.y * tanh_fast(s1v.y + f2.y)
                         + wv.z * tanh_fast(s1v.z + f2.z)
                         + wv.w * tanh_fast(s1v.w + f2.w);
            }
        }
        #pragma unroll
        for (int qi = 0; qi < 2; qi++)
            sc[((qg << 1) + qi) * SV_ + (vh << 6) + v] = acc[qi];
        __syncthreads();
    }

    {
        const int q = tid >> 5, lane = tid & 31;
        float x0 = sc[q*SV_ +      lane];
        float x1 = sc[q*SV_ + 32 + lane];
        float x2 = sc[q*SV_ + 64 + lane];
        float x3 = sc[q*SV_ + 96 + lane];
        float m = fmaxf(fmaxf(x0, x1), fmaxf(x2, x3));
        #pragma unroll
        for (int off = 16; off; off >>= 1)
            m = fmaxf(m, __shfl_xor_sync(0xffffffffu, m, off));
        float e0 = __expf(x0 - m), e1 = __expf(x1 - m);
        float e2 = __expf(x2 - m), e3 = __expf(x3 - m);
        float s = (e0 + e1) + (e2 + e3);
        #pragma unroll
        for (int off = 16; off; off >>= 1)
            s += __shfl_xor_sync(0xffffffffu, s, off);
        float inv = 1.0f / s;
        e0 *= inv; e1 *= inv; e2 *= inv; e3 *= inv;
        sc[q*SV_ +      lane] = e0;
        sc[q*SV_ + 32 + lane] = e1;
        sc[q*SV_ + 64 + lane] = e2;
        sc[q*SV_ + 96 + lane] = e3;
        float* wout = out + CTX_ELEMS + (size_t)(b * SQ_ + q0 + q) * SV_;
        wout[lane]      = e0;
        wout[32 + lane] = e1;
        wout[64 + lane] = e2;
        wout[96 + lane] = e3;
    }
    __syncthreads();

    {
        const int half = tid >> 7;
        const int dg   = tid & 127;
        float4 acc[QT];
        #pragma unroll
        for (int q = 0; q < QT; q++) acc[q] = make_float4(0.f, 0.f, 0.f, 0.f);

        const float* vb  = values + ((size_t)(b * SV_) + (half << 6)) * DV_ + (dg << 2);
        const float* scv = sc + (half << 6);
        #pragma unroll 4
        for (int vv = 0; vv < 64; vv++) {
            float4 val = *(const float4*)(vb + (size_t)vv * DV_);
            #pragma unroll
            for (int q = 0; q < QT; q++) {
                float wq = scv[q * SV_ + vv];
                acc[q].x += wq * val.x;
                acc[q].y += wq * val.y;
                acc[q].z += wq * val.z;
                acc[q].w += wq * val.w;
            }
        }
        if (half) {
            #pragma unroll
            for (int q = 0; q < QT; q++) cbuf[q * 128 + dg] = acc[q];
        }
        __syncthreads();
        if (!half) {
            #pragma unroll
            for (int q = 0; q < QT; q++) {
                float4 o = cbuf[q * 128 + dg];
                o.x += acc[q].x; o.y += acc[q].y;
                o.z += acc[q].z; o.w += acc[q].w;
                *(float4*)&out[(size_t)(b * SQ_ + q0 + q) * DV_ + (dg << 2)] = o;
            }
        }
    }
}

// ========================================================================
extern "C" void kernel_launch(void* const* d_in, const int* in_sizes, int n_in,
                              void* d_out, int out_size)
{
    const float* query  = (const float*)d_in[0];
    const float* values = (const float*)d_in[1];
    const float* W1     = (const float*)d_in[2];
    const float* b1     = (const float*)d_in[3];
    const float* W2     = (const float*)d_in[4];
    const float* b2     = (const float*)d_in[5];
    const float* Vw     = (const float*)d_in[6];
    // d_in[7] = Vb: softmax shift-invariance -> provably cancels. Unused.
    float* out = (float*)d_out;

    dim3 pc_grid(256, 4);
    preconv_kernel<<<pc_grid, 256>>>(query, values, W1, W2);

    cudaFuncSetAttribute(gemm_tc_kernel,
                         cudaFuncAttributeMaxDynamicSharedMemorySize,
                         SM_GEMM_TOTAL);
    dim3 gemm_grid(U_/64, (B_*SQ_)/128, 2);      // 4 x 16 x 2 = 128 CTAs
    gemm_tc_kernel<<<gemm_grid, 256, SM_GEMM_TOTAL>>>(b1, b2);

    const size_t attn_smem = (size_t)SM_TOTAL_F * sizeof(float);
    cudaFuncSetAttribute(attn_kernel,
                         cudaFuncAttributeMaxDynamicSharedMemorySize,
                         (int)attn_smem);
    attn_kernel<<<B_ * (SQ_/QT), 256, attn_smem>>>(values, Vw, out);
}

// round 16
// speedup vs baseline: 1.6680x; 1.0730x over previous
#include <cuda_runtime.h>
#include <cuda_bf16.h>
#include <math.h>
#include <cstdint>

#define B_   16
#define SQ_  128
#define SV_  128
#define DQ_  512
#define DV_  512
#define U_   256
#define QT   8
#define CTX_ELEMS (B_*SQ_*DV_)

typedef unsigned long long ull;

// Scratch (allocation-free rule: __device__ globals)
__device__ float g_s1[B_*SQ_*U_];    // [b][q][u]
__device__ float g_s2[B_*SV_*U_];    // [b][v][u]
// Pre-converted split-bf16 operands
__device__ __nv_bfloat16 g_ah[2][B_*SQ_*DQ_];  // [which][m][k] hi  (which=1 == values!)
__device__ __nv_bfloat16 g_al[2][B_*SQ_*DQ_];  // lo
__device__ __nv_bfloat16 g_wh[2][DQ_*U_];      // [which][k][n] hi
__device__ __nv_bfloat16 g_wl[2][DQ_*U_];      // lo
// Softmax weights, split bf16 (written by attn, read by ctx GEMM)
__device__ __nv_bfloat16 g_wgh[B_*SQ_*SV_];
__device__ __nv_bfloat16 g_wgl[B_*SQ_*SV_];

__device__ __forceinline__ float tanh_fast(float x) {
    float y;
    asm("tanh.approx.f32 %0, %1;" : "=f"(y) : "f"(x));
    return y;
}
__device__ __forceinline__ uint32_t smem_u32(const void* p) {
    uint32_t a;
    asm("{ .reg .u64 t; cvta.to.shared.u64 t, %1; cvt.u32.u64 %0, t; }"
        : "=r"(a) : "l"(p));
    return a;
}
__device__ __forceinline__ void ldsm_x4(uint32_t* r, uint32_t addr) {
    asm volatile("ldmatrix.sync.aligned.m8n8.x4.shared.b16 {%0,%1,%2,%3}, [%4];"
        : "=r"(r[0]), "=r"(r[1]), "=r"(r[2]), "=r"(r[3]) : "r"(addr));
}
__device__ __forceinline__ void ldsm_x4t(uint32_t* r, uint32_t addr) {
    asm volatile("ldmatrix.sync.aligned.m8n8.x4.trans.shared.b16 {%0,%1,%2,%3}, [%4];"
        : "=r"(r[0]), "=r"(r[1]), "=r"(r[2]), "=r"(r[3]) : "r"(addr));
}
__device__ __forceinline__ void mma16816(float* c, const uint32_t* a,
                                         const uint32_t* b) {
    asm volatile(
        "mma.sync.aligned.m16n8k16.row.col.f32.bf16.bf16.f32 "
        "{%0,%1,%2,%3}, {%4,%5,%6,%7}, {%8,%9}, {%0,%1,%2,%3};"
        : "+f"(c[0]), "+f"(c[1]), "+f"(c[2]), "+f"(c[3])
        : "r"(a[0]), "r"(a[1]), "r"(a[2]), "r"(a[3]), "r"(b[0]), "r"(b[1]));
}
__device__ __forceinline__ ull split_pack(float4 a, ull& lp) {
    __nv_bfloat16 h0 = __float2bfloat16(a.x);
    __nv_bfloat16 h1 = __float2bfloat16(a.y);
    __nv_bfloat16 h2 = __float2bfloat16(a.z);
    __nv_bfloat16 h3 = __float2bfloat16(a.w);
    __nv_bfloat16 l0 = __float2bfloat16(a.x - __bfloat162float(h0));
    __nv_bfloat16 l1 = __float2bfloat16(a.y - __bfloat162float(h1));
    __nv_bfloat16 l2 = __float2bfloat16(a.z - __bfloat162float(h2));
    __nv_bfloat16 l3 = __float2bfloat16(a.w - __bfloat162float(h3));
    lp = (ull)__bfloat16_as_ushort(l0) | ((ull)__bfloat16_as_ushort(l1) << 16)
       | ((ull)__bfloat16_as_ushort(l2) << 32) | ((ull)__bfloat16_as_ushort(l3) << 48);
    return (ull)__bfloat16_as_ushort(h0) | ((ull)__bfloat16_as_ushort(h1) << 16)
         | ((ull)__bfloat16_as_ushort(h2) << 32) | ((ull)__bfloat16_as_ushort(h3) << 48);
}

// ========================================================================
// Pre-convert fp32 -> split bf16 (R14, unchanged).
// ========================================================================
__global__ __launch_bounds__(256) void preconv_kernel(
    const float* __restrict__ q, const float* __restrict__ v,
    const float* __restrict__ w1, const float* __restrict__ w2)
{
    const int z = blockIdx.y;
    const float* src = (z == 0) ? q : (z == 1) ? v : (z == 2) ? w1 : w2;
    __nv_bfloat16* dh = (z < 2) ? g_ah[z] : g_wh[z - 2];
    __nv_bfloat16* dl = (z < 2) ? g_al[z] : g_wl[z - 2];
    const int n4 = (z < 2) ? (B_*SQ_*DQ_/4) : (DQ_*U_/4);

    const int stride = gridDim.x * 256;
    int i = blockIdx.x * 256 + threadIdx.x;

    for (; i + 3 * stride < n4; i += 4 * stride) {
        float4 a0 = ((const float4*)src)[i];
        float4 a1 = ((const float4*)src)[i +     stride];
        float4 a2 = ((const float4*)src)[i + 2 * stride];
        float4 a3 = ((const float4*)src)[i + 3 * stride];
        ull l0, h0 = split_pack(a0, l0);
        ull l1, h1 = split_pack(a1, l1);
        ull l2, h2 = split_pack(a2, l2);
        ull l3, h3 = split_pack(a3, l3);
        ((ull*)dh)[i]              = h0;  ((ull*)dl)[i]              = l0;
        ((ull*)dh)[i +     stride] = h1;  ((ull*)dl)[i +     stride] = l1;
        ((ull*)dh)[i + 2 * stride] = h2;  ((ull*)dl)[i + 2 * stride] = l2;
        ((ull*)dh)[i + 3 * stride] = h3;  ((ull*)dl)[i + 3 * stride] = l3;
    }
    for (; i < n4; i += stride) {
        float4 a = ((const float4*)src)[i];
        ull lp, hp = split_pack(a, lp);
        ((ull*)dh)[i] = hp;
        ((ull*)dl)[i] = lp;
    }
}

// ========================================================================
// Tensor-core dual GEMM (R14, unchanged): register-prefetch pipelined.
// ========================================================================
#define KC    128
#define ASTR  272
#define BSTR  144
#define A_HI  0
#define A_LO  (128 * ASTR)
#define BSM_HI (2 * 128 * ASTR)
#define BSM_LO (BSM_HI + KC * BSTR)
#define SM_GEMM_TOTAL (BSM_LO + KC * BSTR)

__global__ __launch_bounds__(256, 1) void gemm_tc_kernel(
    const float* __restrict__ b1, const float* __restrict__ b2)
{
    extern __shared__ char smem[];
    const uint32_t smb = smem_u32(smem);
    const int tid = threadIdx.x;
    const int l   = tid & 31;
    const int w   = tid >> 5;
    const int mw  = w >> 1;
    const int nw  = w & 1;

    const int which = blockIdx.z;
    const __nv_bfloat16* __restrict__ Ah = g_ah[which];
    const __nv_bfloat16* __restrict__ Al = g_al[which];
    const __nv_bfloat16* __restrict__ Wh = g_wh[which];
    const __nv_bfloat16* __restrict__ Wl = g_wl[which];
    const float* __restrict__ bias = which ? b2 : b1;
    float* __restrict__ C          = which ? g_s2 : g_s1;

    const int bm = blockIdx.y * 128;
    const int bn = blockIdx.x * 64;

    float acc[2][4][4];
    #pragma unroll
    for (int mi = 0; mi < 2; mi++)
        #pragma unroll
        for (int ni = 0; ni < 4; ni++)
            #pragma unroll
            for (int j = 0; j < 4; j++) acc[mi][ni][j] = 0.f;

    const int a_row = tid >> 4;
    const int a_kc  = (tid & 15) << 3;
    const int b_k   = tid >> 3;
    const int b_nc  = (tid & 7) << 3;

    uint4 pa_h[8], pa_l[8], pb_h[4], pb_l[4];

    const int arow = mw*32 + (l & 7) + 8*((l >> 3) & 1);
    const uint32_t aoff = (uint32_t)(arow * ASTR + ((l >> 4) << 4));
    const int brow = (l & 7) + 8*((l >> 3) & 1);
    const uint32_t boff = (uint32_t)(brow * BSTR + nw*64 + ((l >> 4) << 4));

    #pragma unroll
    for (int j = 0; j < 8; j++) {
        const size_t g = (size_t)(bm + a_row + j*16) * DQ_ + a_kc;
        pa_h[j] = *(const uint4*)(Ah + g);
        pa_l[j] = *(const uint4*)(Al + g);
    }
    #pragma unroll
    for (int j = 0; j < 4; j++) {
        const size_t g = (size_t)(b_k + j*32) * U_ + bn + b_nc;
        pb_h[j] = *(const uint4*)(Wh + g);
        pb_l[j] = *(const uint4*)(Wl + g);
    }

    #pragma unroll 1
    for (int ch = 0; ch < 4; ch++) {
        __syncthreads();

        #pragma unroll
        for (int j = 0; j < 8; j++) {
            const int off = (a_row + j*16) * ASTR + (a_kc << 1);
            *(uint4*)(smem + A_HI + off) = pa_h[j];
            *(uint4*)(smem + A_LO + off) = pa_l[j];
        }
        #pragma unroll
        for (int j = 0; j < 4; j++) {
            const int off = (b_k + j*32) * BSTR + (b_nc << 1);
            *(uint4*)(smem + BSM_HI + off) = pb_h[j];
            *(uint4*)(smem + BSM_LO + off) = pb_l[j];
        }
        __syncthreads();

        if (ch < 3) {
            const int k0 = (ch + 1) * KC;
            #pragma unroll
            for (int j = 0; j < 8; j++) {
                const size_t g = (size_t)(bm + a_row + j*16) * DQ_ + k0 + a_kc;
                pa_h[j] = *(const uint4*)(Ah + g);
                pa_l[j] = *(const uint4*)(Al + g);
            }
            #pragma unroll
            for (int j = 0; j < 4; j++) {
                const size_t g = (size_t)(k0 + b_k + j*32) * U_ + bn + b_nc;
                pb_h[j] = *(const uint4*)(Wh + g);
                pb_l[j] = *(const uint4*)(Wl + g);
            }
        }

        #pragma unroll 2
        for (int s = 0; s < 8; s++) {
            uint32_t ah[2][4], al[2][4], bh[2][4], bl[2][4];
            const uint32_t as_ = aoff + (uint32_t)(s << 5);
            const uint32_t bs_ = boff + (uint32_t)(s * 16 * BSTR);
            ldsm_x4 (ah[0], smb + A_HI  + as_);
            ldsm_x4 (ah[1], smb + A_HI  + as_ + 16 * ASTR);
            ldsm_x4 (al[0], smb + A_LO  + as_);
            ldsm_x4 (al[1], smb + A_LO  + as_ + 16 * ASTR);
            ldsm_x4t(bh[0], smb + BSM_HI + bs_);
            ldsm_x4t(bh[1], smb + BSM_HI + bs_ + 32);
            ldsm_x4t(bl[0], smb + BSM_LO + bs_);
            ldsm_x4t(bl[1], smb + BSM_LO + bs_ + 32);
            #pragma unroll
            for (int mi = 0; mi < 2; mi++)
                #pragma unroll
                for (int p = 0; p < 2; p++) {
                    mma16816(acc[mi][2*p],   ah[mi], &bh[p][0]);
                    mma16816(acc[mi][2*p],   ah[mi], &bl[p][0]);
                    mma16816(acc[mi][2*p],   al[mi], &bh[p][0]);
                    mma16816(acc[mi][2*p+1], ah[mi], &bh[p][2]);
                    mma16816(acc[mi][2*p+1], ah[mi], &bl[p][2]);
                    mma16816(acc[mi][2*p+1], al[mi], &bh[p][2]);
                }
        }
    }

    #pragma unroll
    for (int mi = 0; mi < 2; mi++) {
        const int r = bm + mw*32 + mi*16 + (l >> 2);
        #pragma unroll
        for (int ni = 0; ni < 4; ni++) {
            const int c = bn + nw*32 + ni*8 + ((l & 3) << 1);
            float2 bb = *(const float2*)(bias + c);
            float2 o0 = make_float2(acc[mi][ni][0] + bb.x, acc[mi][ni][1] + bb.y);
            float2 o1 = make_float2(acc[mi][ni][2] + bb.x, acc[mi][ni][3] + bb.y);
            *(float2*)&C[(size_t)r * U_ + c]       = o0;
            *(float2*)&C[(size_t)(r + 8) * U_ + c] = o1;
        }
    }
}

// ========================================================================
// Attention: score + softmax ONLY (context moved to tensor-core kernel).
// CTA = (b, 8-q tile), grid 256. Writes weights fp32 to out and split
// bf16 to g_wgh/g_wgl for the ctx GEMM.
// ========================================================================
#define S2HSTRIDE 260
#define SM_S1   (64 * S2HSTRIDE)
#define SM_VW   (SM_S1 + QT * U_)
#define SM_SC   (SM_VW + U_)
#define SM_TOTAL_F (SM_SC + QT * SV_)       // 19968 floats = 79872 B

__global__ __launch_bounds__(256, 2) void attn_kernel(
    const float* __restrict__ Vw, float* __restrict__ out)
{
    extern __shared__ float sm[];
    float* s2h = sm;
    float* s1s = sm + SM_S1;
    float* vws = sm + SM_VW;
    float* sc  = sm + SM_SC;

    const int tid = threadIdx.x;
    const int b   = blockIdx.x >> 4;
    const int q0  = (blockIdx.x & 15) << 3;

    const float4* s1g4 = (const float4*)(g_s1 + ((size_t)b * SQ_ + q0) * U_);
    for (int i = tid; i < QT * (U_/4); i += 256)
        ((float4*)s1s)[i] = s1g4[i];
    if (tid < U_/4)
        ((float4*)vws)[tid] = ((const float4*)Vw)[tid];

    #pragma unroll 1
    for (int vh = 0; vh < 2; vh++) {
        const float4* s2g4 =
            (const float4*)(g_s2 + ((size_t)b * SV_ + (vh << 6)) * U_);
        for (int i = tid; i < 64 * (U_/4); i += 256) {
            int v = i >> 6, u4 = i & 63;
            *(float4*)&s2h[v * S2HSTRIDE + (u4 << 2)] = s2g4[i];
        }
        __syncthreads();

        const int v  = tid & 63;
        const int qg = tid >> 6;
        const float* s1q = s1s + (qg << 1) * U_;
        const float* s2r = s2h + v * S2HSTRIDE;
        float acc[2] = {0.f, 0.f};
        #pragma unroll 4
        for (int u = 0; u < U_; u += 4) {
            float4 f2 = *(const float4*)(s2r + u);
            float4 wv = *(const float4*)(vws + u);
            #pragma unroll
            for (int qi = 0; qi < 2; qi++) {
                float4 s1v = *(const float4*)(s1q + qi * U_ + u);
                acc[qi] += wv.x * tanh_fast(s1v.x + f2.x)
                         + wv.y * tanh_fast(s1v.y + f2.y)
                         + wv.z * tanh_fast(s1v.z + f2.z)
                         + wv.w * tanh_fast(s1v.w + f2.w);
            }
        }
        #pragma unroll
        for (int qi = 0; qi < 2; qi++)
            sc[((qg << 1) + qi) * SV_ + (vh << 6) + v] = acc[qi];
        __syncthreads();
    }

    // softmax + weight outputs (fp32 + split bf16)
    {
        const int q = tid >> 5, lane = tid & 31;
        float x0 = sc[q*SV_ +      lane];
        float x1 = sc[q*SV_ + 32 + lane];
        float x2 = sc[q*SV_ + 64 + lane];
        float x3 = sc[q*SV_ + 96 + lane];
        float m = fmaxf(fmaxf(x0, x1), fmaxf(x2, x3));
        #pragma unroll
        for (int off = 16; off; off >>= 1)
            m = fmaxf(m, __shfl_xor_sync(0xffffffffu, m, off));
        float e0 = __expf(x0 - m), e1 = __expf(x1 - m);
        float e2 = __expf(x2 - m), e3 = __expf(x3 - m);
        float s = (e0 + e1) + (e2 + e3);
        #pragma unroll
        for (int off = 16; off; off >>= 1)
            s += __shfl_xor_sync(0xffffffffu, s, off);
        float inv = 1.0f / s;
        e0 *= inv; e1 *= inv; e2 *= inv; e3 *= inv;

        const size_t row = (size_t)(b * SQ_ + q0 + q) * SV_;
        float* wout = out + CTX_ELEMS + row;
        wout[lane]      = e0;
        wout[32 + lane] = e1;
        wout[64 + lane] = e2;
        wout[96 + lane] = e3;

        __nv_bfloat16* wh = g_wgh + row;
        __nv_bfloat16* wl = g_wgl + row;
        __nv_bfloat16 h0 = __float2bfloat16(e0);
        __nv_bfloat16 h1 = __float2bfloat16(e1);
        __nv_bfloat16 h2 = __float2bfloat16(e2);
        __nv_bfloat16 h3 = __float2bfloat16(e3);
        wh[lane]      = h0;  wl[lane]      = __float2bfloat16(e0 - __bfloat162float(h0));
        wh[32 + lane] = h1;  wl[32 + lane] = __float2bfloat16(e1 - __bfloat162float(h1));
        wh[64 + lane] = h2;  wl[64 + lane] = __float2bfloat16(e2 - __bfloat162float(h2));
        wh[96 + lane] = h3;  wl[96 + lane] = __float2bfloat16(e3 - __bfloat162float(h3));
    }
}

// ========================================================================
// Context GEMM (tensor core): ctx[b] = W[b](128q x 128v) @ values[b](128v x 512d)
// A = g_wgh/g_wgl (weights split), B = g_ah[1]/g_al[1] (values split, from
// preconv). Single K-chunk. grid (8 d-tiles, 16 batches), 256 threads.
// ========================================================================
__global__ __launch_bounds__(256, 1) void ctx_tc_kernel(float* __restrict__ out)
{
    extern __shared__ char smem[];
    const uint32_t smb = smem_u32(smem);
    const int tid = threadIdx.x;
    const int l   = tid & 31;
    const int w   = tid >> 5;
    const int mw  = w >> 1;
    const int nw  = w & 1;

    const int b  = blockIdx.y;
    const int bn = blockIdx.x * 64;

    const __nv_bfloat16* __restrict__ Ah = g_wgh + (size_t)b * SQ_ * SV_;
    const __nv_bfloat16* __restrict__ Al = g_wgl + (size_t)b * SQ_ * SV_;
    const __nv_bfloat16* __restrict__ Bh = g_ah[1] + (size_t)b * SV_ * DV_;
    const __nv_bfloat16* __restrict__ Bl = g_al[1] + (size_t)b * SV_ * DV_;

    float acc[2][4][4];
    #pragma unroll
    for (int mi = 0; mi < 2; mi++)
        #pragma unroll
        for (int ni = 0; ni < 4; ni++)
            #pragma unroll
            for (int j = 0; j < 4; j++) acc[mi][ni][j] = 0.f;

    // stage A: weights [128q x 128v] hi/lo (rows of 128 bf16 = 256B)
    #pragma unroll 4
    for (int i = tid; i < 128 * 16; i += 256) {
        const int row = i >> 4;
        const int kc  = (i & 15) << 3;
        const size_t g = (size_t)row * SV_ + kc;
        const int off = row * ASTR + (kc << 1);
        *(uint4*)(smem + A_HI + off) = *(const uint4*)(Ah + g);
        *(uint4*)(smem + A_LO + off) = *(const uint4*)(Al + g);
    }
    // stage B: values [128v x 64d-tile] hi/lo
    #pragma unroll 4
    for (int i = tid; i < 128 * 8; i += 256) {
        const int k  = i >> 3;
        const int nc = (i & 7) << 3;
        const size_t g = (size_t)k * DV_ + bn + nc;
        const int off = k * BSTR + (nc << 1);
        *(uint4*)(smem + BSM_HI + off) = *(const uint4*)(Bh + g);
        *(uint4*)(smem + BSM_LO + off) = *(const uint4*)(Bl + g);
    }
    __syncthreads();

    const int arow = mw*32 + (l & 7) + 8*((l >> 3) & 1);
    const uint32_t aoff = (uint32_t)(arow * ASTR + ((l >> 4) << 4));
    const int brow = (l & 7) + 8*((l >> 3) & 1);
    const uint32_t boff = (uint32_t)(brow * BSTR + nw*64 + ((l >> 4) << 4));

    #pragma unroll 2
    for (int s = 0; s < 8; s++) {
        uint32_t ah[2][4], al[2][4], bh[2][4], bl[2][4];
        const uint32_t as_ = aoff + (uint32_t)(s << 5);
        const uint32_t bs_ = boff + (uint32_t)(s * 16 * BSTR);
        ldsm_x4 (ah[0], smb + A_HI  + as_);
        ldsm_x4 (ah[1], smb + A_HI  + as_ + 16 * ASTR);
        ldsm_x4 (al[0], smb + A_LO  + as_);
        ldsm_x4 (al[1], smb + A_LO  + as_ + 16 * ASTR);
        ldsm_x4t(bh[0], smb + BSM_HI + bs_);
        ldsm_x4t(bh[1], smb + BSM_HI + bs_ + 32);
        ldsm_x4t(bl[0], smb + BSM_LO + bs_);
        ldsm_x4t(bl[1], smb + BSM_LO + bs_ + 32);
        #pragma unroll
        for (int mi = 0; mi < 2; mi++)
            #pragma unroll
            for (int p = 0; p < 2; p++) {
                mma16816(acc[mi][2*p],   ah[mi], &bh[p][0]);
                mma16816(acc[mi][2*p],   ah[mi], &bl[p][0]);
                mma16816(acc[mi][2*p],   al[mi], &bh[p][0]);
                mma16816(acc[mi][2*p+1], ah[mi], &bh[p][2]);
                mma16816(acc[mi][2*p+1], ah[mi], &bl[p][2]);
                mma16816(acc[mi][2*p+1], al[mi], &bh[p][2]);
            }
    }

    // epilogue: store context fp32 (no bias)
    #pragma unroll
    for (int mi = 0; mi < 2; mi++) {
        const int r = mw*32 + mi*16 + (l >> 2);
        #pragma unroll
        for (int ni = 0; ni < 4; ni++) {
            const int c = bn + nw*32 + ni*8 + ((l & 3) << 1);
            *(float2*)&out[(size_t)(b * SQ_ + r) * DV_ + c] =
                make_float2(acc[mi][ni][0], acc[mi][ni][1]);
            *(float2*)&out[(size_t)(b * SQ_ + r + 8) * DV_ + c] =
                make_float2(acc[mi][ni][2], acc[mi][ni][3]);
        }
    }
}

// ========================================================================
extern "C" void kernel_launch(void* const* d_in, const int* in_sizes, int n_in,
                              void* d_out, int out_size)
{
    const float* query  = (const float*)d_in[0];
    const float* values = (const float*)d_in[1];
    const float* W1     = (const float*)d_in[2];
    const float* b1     = (const float*)d_in[3];
    const float* W2     = (const float*)d_in[4];
    const float* b2     = (const float*)d_in[5];
    const float* Vw     = (const float*)d_in[6];
    // d_in[7] = Vb: softmax shift-invariance -> provably cancels. Unused.
    float* out = (float*)d_out;
    (void)values;

    dim3 pc_grid(256, 4);
    preconv_kernel<<<pc_grid, 256>>>(query, values, W1, W2);

    cudaFuncSetAttribute(gemm_tc_kernel,
                         cudaFuncAttributeMaxDynamicSharedMemorySize,
                         SM_GEMM_TOTAL);
    dim3 gemm_grid(U_/64, (B_*SQ_)/128, 2);
    gemm_tc_kernel<<<gemm_grid, 256, SM_GEMM_TOTAL>>>(b1, b2);

    const size_t attn_smem = (size_t)SM_TOTAL_F * sizeof(float);
    cudaFuncSetAttribute(attn_kernel,
                         cudaFuncAttributeMaxDynamicSharedMemorySize,
                         (int)attn_smem);
    attn_kernel<<<B_ * (SQ_/QT), 256, attn_smem>>>(Vw, out);

    cudaFuncSetAttribute(ctx_tc_kernel,
                         cudaFuncAttributeMaxDynamicSharedMemorySize,
                         SM_GEMM_TOTAL);
    dim3 ctx_grid(DV_/64, B_);
    ctx_tc_kernel<<<ctx_grid, 256, SM_GEMM_TOTAL>>>(out);
}

// round 17
// speedup vs baseline: 1.6893x; 1.0128x over previous
#include <cuda_runtime.h>
#include <cuda_bf16.h>
#include <math.h>
#include <cstdint>

#define B_   16
#define SQ_  128
#define SV_  128
#define DQ_  512
#define DV_  512
#define U_   256
#define QT   8
#define CTX_ELEMS (B_*SQ_*DV_)

typedef unsigned long long ull;

// Scratch (allocation-free rule: __device__ globals)
__device__ float g_s1[B_*SQ_*U_];    // [b][q][u]
__device__ float g_s2[B_*SV_*U_];    // [b][v][u]
// Pre-converted split-bf16 operands
__device__ __nv_bfloat16 g_ah[2][B_*SQ_*DQ_];  // [which][m][k] hi  (which=1 == values!)
__device__ __nv_bfloat16 g_al[2][B_*SQ_*DQ_];  // lo
__device__ __nv_bfloat16 g_wh[2][DQ_*U_];      // [which][k][n] hi
__device__ __nv_bfloat16 g_wl[2][DQ_*U_];      // lo
// Softmax weights, split bf16 (written by attn, read by ctx GEMM)
__device__ __nv_bfloat16 g_wgh[B_*SQ_*SV_];
__device__ __nv_bfloat16 g_wgl[B_*SQ_*SV_];

__device__ __forceinline__ float tanh_fast(float x) {
    float y;
    asm("tanh.approx.f32 %0, %1;" : "=f"(y) : "f"(x));
    return y;
}
__device__ __forceinline__ uint32_t smem_u32(const void* p) {
    uint32_t a;
    asm("{ .reg .u64 t; cvta.to.shared.u64 t, %1; cvt.u32.u64 %0, t; }"
        : "=r"(a) : "l"(p));
    return a;
}
__device__ __forceinline__ void ldsm_x4(uint32_t* r, uint32_t addr) {
    asm volatile("ldmatrix.sync.aligned.m8n8.x4.shared.b16 {%0,%1,%2,%3}, [%4];"
        : "=r"(r[0]), "=r"(r[1]), "=r"(r[2]), "=r"(r[3]) : "r"(addr));
}
__device__ __forceinline__ void ldsm_x4t(uint32_t* r, uint32_t addr) {
    asm volatile("ldmatrix.sync.aligned.m8n8.x4.trans.shared.b16 {%0,%1,%2,%3}, [%4];"
        : "=r"(r[0]), "=r"(r[1]), "=r"(r[2]), "=r"(r[3]) : "r"(addr));
}
__device__ __forceinline__ void mma16816(float* c, const uint32_t* a,
                                         const uint32_t* b) {
    asm volatile(
        "mma.sync.aligned.m16n8k16.row.col.f32.bf16.bf16.f32 "
        "{%0,%1,%2,%3}, {%4,%5,%6,%7}, {%8,%9}, {%0,%1,%2,%3};"
        : "+f"(c[0]), "+f"(c[1]), "+f"(c[2]), "+f"(c[3])
        : "r"(a[0]), "r"(a[1]), "r"(a[2]), "r"(a[3]), "r"(b[0]), "r"(b[1]));
}
__device__ __forceinline__ ull split_pack(float4 a, ull& lp) {
    __nv_bfloat16 h0 = __float2bfloat16(a.x);
    __nv_bfloat16 h1 = __float2bfloat16(a.y);
    __nv_bfloat16 h2 = __float2bfloat16(a.z);
    __nv_bfloat16 h3 = __float2bfloat16(a.w);
    __nv_bfloat16 l0 = __float2bfloat16(a.x - __bfloat162float(h0));
    __nv_bfloat16 l1 = __float2bfloat16(a.y - __bfloat162float(h1));
    __nv_bfloat16 l2 = __float2bfloat16(a.z - __bfloat162float(h2));
    __nv_bfloat16 l3 = __float2bfloat16(a.w - __bfloat162float(h3));
    lp = (ull)__bfloat16_as_ushort(l0) | ((ull)__bfloat16_as_ushort(l1) << 16)
       | ((ull)__bfloat16_as_ushort(l2) << 32) | ((ull)__bfloat16_as_ushort(l3) << 48);
    return (ull)__bfloat16_as_ushort(h0) | ((ull)__bfloat16_as_ushort(h1) << 16)
         | ((ull)__bfloat16_as_ushort(h2) << 32) | ((ull)__bfloat16_as_ushort(h3) << 48);
}

// ========================================================================
// Pre-convert fp32 -> split bf16 (R14, unchanged).
// ========================================================================
__global__ __launch_bounds__(256) void preconv_kernel(
    const float* __restrict__ q, const float* __restrict__ v,
    const float* __restrict__ w1, const float* __restrict__ w2)
{
    const int z = blockIdx.y;
    const float* src = (z == 0) ? q : (z == 1) ? v : (z == 2) ? w1 : w2;
    __nv_bfloat16* dh = (z < 2) ? g_ah[z] : g_wh[z - 2];
    __nv_bfloat16* dl = (z < 2) ? g_al[z] : g_wl[z - 2];
    const int n4 = (z < 2) ? (B_*SQ_*DQ_/4) : (DQ_*U_/4);

    const int stride = gridDim.x * 256;
    int i = blockIdx.x * 256 + threadIdx.x;

    for (; i + 3 * stride < n4; i += 4 * stride) {
        float4 a0 = ((const float4*)src)[i];
        float4 a1 = ((const float4*)src)[i +     stride];
        float4 a2 = ((const float4*)src)[i + 2 * stride];
        float4 a3 = ((const float4*)src)[i + 3 * stride];
        ull l0, h0 = split_pack(a0, l0);
        ull l1, h1 = split_pack(a1, l1);
        ull l2, h2 = split_pack(a2, l2);
        ull l3, h3 = split_pack(a3, l3);
        ((ull*)dh)[i]              = h0;  ((ull*)dl)[i]              = l0;
        ((ull*)dh)[i +     stride] = h1;  ((ull*)dl)[i +     stride] = l1;
        ((ull*)dh)[i + 2 * stride] = h2;  ((ull*)dl)[i + 2 * stride] = l2;
        ((ull*)dh)[i + 3 * stride] = h3;  ((ull*)dl)[i + 3 * stride] = l3;
    }
    for (; i < n4; i += stride) {
        float4 a = ((const float4*)src)[i];
        ull lp, hp = split_pack(a, lp);
        ((ull*)dh)[i] = hp;
        ((ull*)dl)[i] = lp;
    }
}

// ========================================================================
// Tensor-core dual GEMM (R14, unchanged): register-prefetch pipelined.
// ========================================================================
#define KC    128
#define ASTR  272
#define BSTR  144
#define A_HI  0
#define A_LO  (128 * ASTR)
#define BSM_HI (2 * 128 * ASTR)
#define BSM_LO (BSM_HI + KC * BSTR)
#define SM_GEMM_TOTAL (BSM_LO + KC * BSTR)

__global__ __launch_bounds__(256, 1) void gemm_tc_kernel(
    const float* __restrict__ b1, const float* __restrict__ b2)
{
    extern __shared__ char smem[];
    const uint32_t smb = smem_u32(smem);
    const int tid = threadIdx.x;
    const int l   = tid & 31;
    const int w   = tid >> 5;
    const int mw  = w >> 1;
    const int nw  = w & 1;

    const int which = blockIdx.z;
    const __nv_bfloat16* __restrict__ Ah = g_ah[which];
    const __nv_bfloat16* __restrict__ Al = g_al[which];
    const __nv_bfloat16* __restrict__ Wh = g_wh[which];
    const __nv_bfloat16* __restrict__ Wl = g_wl[which];
    const float* __restrict__ bias = which ? b2 : b1;
    float* __restrict__ C          = which ? g_s2 : g_s1;

    const int bm = blockIdx.y * 128;
    const int bn = blockIdx.x * 64;

    float acc[2][4][4];
    #pragma unroll
    for (int mi = 0; mi < 2; mi++)
        #pragma unroll
        for (int ni = 0; ni < 4; ni++)
            #pragma unroll
            for (int j = 0; j < 4; j++) acc[mi][ni][j] = 0.f;

    const int a_row = tid >> 4;
    const int a_kc  = (tid & 15) << 3;
    const int b_k   = tid >> 3;
    const int b_nc  = (tid & 7) << 3;

    uint4 pa_h[8], pa_l[8], pb_h[4], pb_l[4];

    const int arow = mw*32 + (l & 7) + 8*((l >> 3) & 1);
    const uint32_t aoff = (uint32_t)(arow * ASTR + ((l >> 4) << 4));
    const int brow = (l & 7) + 8*((l >> 3) & 1);
    const uint32_t boff = (uint32_t)(brow * BSTR + nw*64 + ((l >> 4) << 4));

    #pragma unroll
    for (int j = 0; j < 8; j++) {
        const size_t g = (size_t)(bm + a_row + j*16) * DQ_ + a_kc;
        pa_h[j] = *(const uint4*)(Ah + g);
        pa_l[j] = *(const uint4*)(Al + g);
    }
    #pragma unroll
    for (int j = 0; j < 4; j++) {
        const size_t g = (size_t)(b_k + j*32) * U_ + bn + b_nc;
        pb_h[j] = *(const uint4*)(Wh + g);
        pb_l[j] = *(const uint4*)(Wl + g);
    }

    #pragma unroll 1
    for (int ch = 0; ch < 4; ch++) {
        __syncthreads();

        #pragma unroll
        for (int j = 0; j < 8; j++) {
            const int off = (a_row + j*16) * ASTR + (a_kc << 1);
            *(uint4*)(smem + A_HI + off) = pa_h[j];
            *(uint4*)(smem + A_LO + off) = pa_l[j];
        }
        #pragma unroll
        for (int j = 0; j < 4; j++) {
            const int off = (b_k + j*32) * BSTR + (b_nc << 1);
            *(uint4*)(smem + BSM_HI + off) = pb_h[j];
            *(uint4*)(smem + BSM_LO + off) = pb_l[j];
        }
        __syncthreads();

        if (ch < 3) {
            const int k0 = (ch + 1) * KC;
            #pragma unroll
            for (int j = 0; j < 8; j++) {
                const size_t g = (size_t)(bm + a_row + j*16) * DQ_ + k0 + a_kc;
                pa_h[j] = *(const uint4*)(Ah + g);
                pa_l[j] = *(const uint4*)(Al + g);
            }
            #pragma unroll
            for (int j = 0; j < 4; j++) {
                const size_t g = (size_t)(k0 + b_k + j*32) * U_ + bn + b_nc;
                pb_h[j] = *(const uint4*)(Wh + g);
                pb_l[j] = *(const uint4*)(Wl + g);
            }
        }

        #pragma unroll 2
        for (int s = 0; s < 8; s++) {
            uint32_t ah[2][4], al[2][4], bh[2][4], bl[2][4];
            const uint32_t as_ = aoff + (uint32_t)(s << 5);
            const uint32_t bs_ = boff + (uint32_t)(s * 16 * BSTR);
            ldsm_x4 (ah[0], smb + A_HI  + as_);
            ldsm_x4 (ah[1], smb + A_HI  + as_ + 16 * ASTR);
            ldsm_x4 (al[0], smb + A_LO  + as_);
            ldsm_x4 (al[1], smb + A_LO  + as_ + 16 * ASTR);
            ldsm_x4t(bh[0], smb + BSM_HI + bs_);
            ldsm_x4t(bh[1], smb + BSM_HI + bs_ + 32);
            ldsm_x4t(bl[0], smb + BSM_LO + bs_);
            ldsm_x4t(bl[1], smb + BSM_LO + bs_ + 32);
            #pragma unroll
            for (int mi = 0; mi < 2; mi++)
                #pragma unroll
                for (int p = 0; p < 2; p++) {
                    mma16816(acc[mi][2*p],   ah[mi], &bh[p][0]);
                    mma16816(acc[mi][2*p],   ah[mi], &bl[p][0]);
                    mma16816(acc[mi][2*p],   al[mi], &bh[p][0]);
                    mma16816(acc[mi][2*p+1], ah[mi], &bh[p][2]);
                    mma16816(acc[mi][2*p+1], ah[mi], &bl[p][2]);
                    mma16816(acc[mi][2*p+1], al[mi], &bh[p][2]);
                }
        }
    }

    #pragma unroll
    for (int mi = 0; mi < 2; mi++) {
        const int r = bm + mw*32 + mi*16 + (l >> 2);
        #pragma unroll
        for (int ni = 0; ni < 4; ni++) {
            const int c = bn + nw*32 + ni*8 + ((l & 3) << 1);
            float2 bb = *(const float2*)(bias + c);
            float2 o0 = make_float2(acc[mi][ni][0] + bb.x, acc[mi][ni][1] + bb.y);
            float2 o1 = make_float2(acc[mi][ni][2] + bb.x, acc[mi][ni][3] + bb.y);
            *(float2*)&C[(size_t)r * U_ + c]       = o0;
            *(float2*)&C[(size_t)(r + 8) * U_ + c] = o1;
        }
    }
}

// ========================================================================
// Attention: score + softmax (R16, unchanged). CTA = (b, 8-q), grid 256.
// ========================================================================
#define S2HSTRIDE 260
#define SM_S1   (64 * S2HSTRIDE)
#define SM_VW   (SM_S1 + QT * U_)
#define SM_SC   (SM_VW + U_)
#define SM_TOTAL_F (SM_SC + QT * SV_)       // 79872 B

__global__ __launch_bounds__(256, 2) void attn_kernel(
    const float* __restrict__ Vw, float* __restrict__ out)
{
    extern __shared__ float sm[];
    float* s2h = sm;
    float* s1s = sm + SM_S1;
    float* vws = sm + SM_VW;
    float* sc  = sm + SM_SC;

    const int tid = threadIdx.x;
    const int b   = blockIdx.x >> 4;
    const int q0  = (blockIdx.x & 15) << 3;

    const float4* s1g4 = (const float4*)(g_s1 + ((size_t)b * SQ_ + q0) * U_);
    for (int i = tid; i < QT * (U_/4); i += 256)
        ((float4*)s1s)[i] = s1g4[i];
    if (tid < U_/4)
        ((float4*)vws)[tid] = ((const float4*)Vw)[tid];

    #pragma unroll 1
    for (int vh = 0; vh < 2; vh++) {
        const float4* s2g4 =
            (const float4*)(g_s2 + ((size_t)b * SV_ + (vh << 6)) * U_);
        for (int i = tid; i < 64 * (U_/4); i += 256) {
            int v = i >> 6, u4 = i & 63;
            *(float4*)&s2h[v * S2HSTRIDE + (u4 << 2)] = s2g4[i];
        }
        __syncthreads();

        const int v  = tid & 63;
        const int qg = tid >> 6;
        const float* s1q = s1s + (qg << 1) * U_;
        const float* s2r = s2h + v * S2HSTRIDE;
        float acc[2] = {0.f, 0.f};
        #pragma unroll 4
        for (int u = 0; u < U_; u += 4) {
            float4 f2 = *(const float4*)(s2r + u);
            float4 wv = *(const float4*)(vws + u);
            #pragma unroll
            for (int qi = 0; qi < 2; qi++) {
                float4 s1v = *(const float4*)(s1q + qi * U_ + u);
                acc[qi] += wv.x * tanh_fast(s1v.x + f2.x)
                         + wv.y * tanh_fast(s1v.y + f2.y)
                         + wv.z * tanh_fast(s1v.z + f2.z)
                         + wv.w * tanh_fast(s1v.w + f2.w);
            }
        }
        #pragma unroll
        for (int qi = 0; qi < 2; qi++)
            sc[((qg << 1) + qi) * SV_ + (vh << 6) + v] = acc[qi];
        __syncthreads();
    }

    // softmax + weight outputs (fp32 + split bf16)
    {
        const int q = tid >> 5, lane = tid & 31;
        float x0 = sc[q*SV_ +      lane];
        float x1 = sc[q*SV_ + 32 + lane];
        float x2 = sc[q*SV_ + 64 + lane];
        float x3 = sc[q*SV_ + 96 + lane];
        float m = fmaxf(fmaxf(x0, x1), fmaxf(x2, x3));
        #pragma unroll
        for (int off = 16; off; off >>= 1)
            m = fmaxf(m, __shfl_xor_sync(0xffffffffu, m, off));
        float e0 = __expf(x0 - m), e1 = __expf(x1 - m);
        float e2 = __expf(x2 - m), e3 = __expf(x3 - m);
        float s = (e0 + e1) + (e2 + e3);
        #pragma unroll
        for (int off = 16; off; off >>= 1)
            s += __shfl_xor_sync(0xffffffffu, s, off);
        float inv = 1.0f / s;
        e0 *= inv; e1 *= inv; e2 *= inv; e3 *= inv;

        const size_t row = (size_t)(b * SQ_ + q0 + q) * SV_;
        float* wout = out + CTX_ELEMS + row;
        wout[lane]      = e0;
        wout[32 + lane] = e1;
        wout[64 + lane] = e2;
        wout[96 + lane] = e3;

        __nv_bfloat16* wh = g_wgh + row;
        __nv_bfloat16* wl = g_wgl + row;
        __nv_bfloat16 h0 = __float2bfloat16(e0);
        __nv_bfloat16 h1 = __float2bfloat16(e1);
        __nv_bfloat16 h2 = __float2bfloat16(e2);
        __nv_bfloat16 h3 = __float2bfloat16(e3);
        wh[lane]      = h0;  wl[lane]      = __float2bfloat16(e0 - __bfloat162float(h0));
        wh[32 + lane] = h1;  wl[32 + lane] = __float2bfloat16(e1 - __bfloat162float(h1));
        wh[64 + lane] = h2;  wl[64 + lane] = __float2bfloat16(e2 - __bfloat162float(h2));
        wh[96 + lane] = h3;  wl[96 + lane] = __float2bfloat16(e3 - __bfloat162float(h3));
    }
}

// ========================================================================
// Context GEMM v2: M=64 (q-half) tiles -> 256 CTAs, 128 threads (4 warps,
// 2m x 2n), 2 CTAs/SM co-resident (staging of one overlaps MMA of other).
// A = g_wgh/g_wgl (weights), B = g_ah[1]/g_al[1] (values). Single K=128.
// ========================================================================
#define CA_HI  0
#define CA_LO  (64 * ASTR)                  // 17408
#define CB_HI  (2 * 64 * ASTR)              // 34816
#define CB_LO  (CB_HI + 128 * BSTR)         // 53248
#define SM_CTX_TOTAL (CB_LO + 128 * BSTR)   // 71680 B

__global__ __launch_bounds__(128, 2) void ctx_tc_kernel(float* __restrict__ out)
{
    extern __shared__ char smem[];
    const uint32_t smb = smem_u32(smem);
    const int tid = threadIdx.x;
    const int l   = tid & 31;
    const int w   = tid >> 5;
    const int mw  = w >> 1;          // 0..1
    const int nw  = w & 1;           // 0..1

    const int b  = blockIdx.y;
    const int bn = blockIdx.x * 64;
    const int qh = blockIdx.z;       // 0/1 -> q rows qh*64
    const int m0 = qh * 64;

    const __nv_bfloat16* __restrict__ Ah = g_wgh + (size_t)(b * SQ_ + m0) * SV_;
    const __nv_bfloat16* __restrict__ Al = g_wgl + (size_t)(b * SQ_ + m0) * SV_;
    const __nv_bfloat16* __restrict__ Bh = g_ah[1] + (size_t)b * SV_ * DV_;
    const __nv_bfloat16* __restrict__ Bl = g_al[1] + (size_t)b * SV_ * DV_;

    float acc[2][4][4];
    #pragma unroll
    for (int mi = 0; mi < 2; mi++)
        #pragma unroll
        for (int ni = 0; ni < 4; ni++)
            #pragma unroll
            for (int j = 0; j < 4; j++) acc[mi][ni][j] = 0.f;

    // stage A: weights [64q x 128v] hi/lo
    #pragma unroll 8
    for (int i = tid; i < 64 * 16; i += 128) {
        const int row = i >> 4;
        const int kc  = (i & 15) << 3;
        const size_t g = (size_t)row * SV_ + kc;
        const int off = row * ASTR + (kc << 1);
        *(uint4*)(smem + CA_HI + off) = *(const uint4*)(Ah + g);
        *(uint4*)(smem + CA_LO + off) = *(const uint4*)(Al + g);
    }
    // stage B: values [128v x 64d-tile] hi/lo
    #pragma unroll 8
    for (int i = tid; i < 128 * 8; i += 128) {
        const int k  = i >> 3;
        const int nc = (i & 7) << 3;
        const size_t g = (size_t)k * DV_ + bn + nc;
        const int off = k * BSTR + (nc << 1);
        *(uint4*)(smem + CB_HI + off) = *(const uint4*)(Bh + g);
        *(uint4*)(smem + CB_LO + off) = *(const uint4*)(Bl + g);
    }
    __syncthreads();

    const int arow = mw*32 + (l & 7) + 8*((l >> 3) & 1);
    const uint32_t aoff = (uint32_t)(arow * ASTR + ((l >> 4) << 4));
    const int brow = (l & 7) + 8*((l >> 3) & 1);
    const uint32_t boff = (uint32_t)(brow * BSTR + nw*64 + ((l >> 4) << 4));

    #pragma unroll 2
    for (int s = 0; s < 8; s++) {
        uint32_t ah[2][4], al[2][4], bh[2][4], bl[2][4];
        const uint32_t as_ = aoff + (uint32_t)(s << 5);
        const uint32_t bs_ = boff + (uint32_t)(s * 16 * BSTR);
        ldsm_x4 (ah[0], smb + CA_HI + as_);
        ldsm_x4 (ah[1], smb + CA_HI + as_ + 16 * ASTR);
        ldsm_x4 (al[0], smb + CA_LO + as_);
        ldsm_x4 (al[1], smb + CA_LO + as_ + 16 * ASTR);
        ldsm_x4t(bh[0], smb + CB_HI + bs_);
        ldsm_x4t(bh[1], smb + CB_HI + bs_ + 32);
        ldsm_x4t(bl[0], smb + CB_LO + bs_);
        ldsm_x4t(bl[1], smb + CB_LO + bs_ + 32);
        #pragma unroll
        for (int mi = 0; mi < 2; mi++)
            #pragma unroll
            for (int p = 0; p < 2; p++) {
                mma16816(acc[mi][2*p],   ah[mi], &bh[p][0]);
                mma16816(acc[mi][2*p],   ah[mi], &bl[p][0]);
                mma16816(acc[mi][2*p],   al[mi], &bh[p][0]);
                mma16816(acc[mi][2*p+1], ah[mi], &bh[p][2]);
                mma16816(acc[mi][2*p+1], ah[mi], &bl[p][2]);
                mma16816(acc[mi][2*p+1], al[mi], &bh[p][2]);
            }
    }

    // epilogue: store context fp32
    #pragma unroll
    for (int mi = 0; mi < 2; mi++) {
        const int r = m0 + mw*32 + mi*16 + (l >> 2);
        #pragma unroll
        for (int ni = 0; ni < 4; ni++) {
            const int c = bn + nw*32 + ni*8 + ((l & 3) << 1);
            *(float2*)&out[(size_t)(b * SQ_ + r) * DV_ + c] =
                make_float2(acc[mi][ni][0], acc[mi][ni][1]);
            *(float2*)&out[(size_t)(b * SQ_ + r + 8) * DV_ + c] =
                make_float2(acc[mi][ni][2], acc[mi][ni][3]);
        }
    }
}

// ========================================================================
extern "C" void kernel_launch(void* const* d_in, const int* in_sizes, int n_in,
                              void* d_out, int out_size)
{
    const float* query  = (const float*)d_in[0];
    const float* values = (const float*)d_in[1];
    const float* W1     = (const float*)d_in[2];
    const float* b1     = (const float*)d_in[3];
    const float* W2     = (const float*)d_in[4];
    const float* b2     = (const float*)d_in[5];
    const float* Vw     = (const float*)d_in[6];
    // d_in[7] = Vb: softmax shift-invariance -> provably cancels. Unused.
    float* out = (float*)d_out;

    dim3 pc_grid(256, 4);
    preconv_kernel<<<pc_grid, 256>>>(query, values, W1, W2);

    cudaFuncSetAttribute(gemm_tc_kernel,
                         cudaFuncAttributeMaxDynamicSharedMemorySize,
                         SM_GEMM_TOTAL);
    dim3 gemm_grid(U_/64, (B_*SQ_)/128, 2);
    gemm_tc_kernel<<<gemm_grid, 256, SM_GEMM_TOTAL>>>(b1, b2);

    const size_t attn_smem = (size_t)SM_TOTAL_F * sizeof(float);
    cudaFuncSetAttribute(attn_kernel,
                         cudaFuncAttributeMaxDynamicSharedMemorySize,
                         (int)attn_smem);
    attn_kernel<<<B_ * (SQ_/QT), 256, attn_smem>>>(Vw, out);

    cudaFuncSetAttribute(ctx_tc_kernel,
                         cudaFuncAttributeMaxDynamicSharedMemorySize,
                         SM_CTX_TOTAL);
    dim3 ctx_grid(DV_/64, B_, 2);            // 8 x 16 x 2 = 256 CTAs
    ctx_tc_kernel<<<ctx_grid, 128, SM_CTX_TOTAL>>>(out);
}